// round 1
// baseline (speedup 1.0000x reference)
#include <cuda_runtime.h>
#include <math.h>

// ---------------- dims ----------------
#define BB   8
#define NNODE 1024
#define DD   256
#define HH   8
#define DHH  32
#define DFFX 1024
#define LGN  2
#define LTN  2

// ---------------- scratch (device globals; no runtime allocation) ----------------
__device__ float    g_XC[BB*NNODE*DD];          // current x
__device__ float    g_HB[BB*NNODE*HH*DD];       // GAT per-head features h [b,n,h,c]
__device__ float    g_T2[BB*NNODE*HH*DD];       // GAT per-head aggregated out
__device__ float    g_AS[BB*NNODE*HH];
__device__ float    g_AD[BB*NNODE*HH];
__device__ float    g_SC[(size_t)BB*HH*NNODE*NNODE]; // scores / alpha (268MB)
__device__ float    g_Q [BB*NNODE*DD];
__device__ float    g_K [BB*NNODE*DD];
__device__ float    g_V [BB*NNODE*DD];
__device__ float    g_AO[BB*NNODE*DD];
__device__ float    g_Y [BB*NNODE*DD];
__device__ float    g_FF[BB*NNODE*DFFX];
__device__ unsigned g_BITS[BB*NNODE*(NNODE/32)]; // adjacency A_ts packed over s

// ---------------- helpers ----------------
__device__ __forceinline__ float block_sum256(float v, float* sm) {
    #pragma unroll
    for (int o = 16; o; o >>= 1) v += __shfl_xor_sync(0xffffffffu, v, o);
    int w = threadIdx.x >> 5;
    if ((threadIdx.x & 31) == 0) sm[w] = v;
    __syncthreads();
    if (threadIdx.x < 8) {
        v = sm[threadIdx.x];
        #pragma unroll
        for (int o = 4; o; o >>= 1) v += __shfl_xor_sync(0xffu, v, o);
        if (threadIdx.x == 0) sm[0] = v;
    }
    __syncthreads();
    v = sm[0];
    __syncthreads();
    return v;
}

// ---------------- adjacency pack: bits[b][t][s/32] ----------------
__global__ void pack_adj_k(const int* __restrict__ mask, unsigned* __restrict__ bits) {
    int idx = blockIdx.x * blockDim.x + threadIdx.x; // B*32*N threads
    int t  = idx & (NNODE - 1);
    int sw = (idx >> 10) & 31;
    int b  = idx >> 15;
    const int* mp = mask + ((size_t)b * NNODE + (size_t)sw * 32) * NNODE + t;
    unsigned w = 0;
    #pragma unroll
    for (int i = 0; i < 32; i++)
        if (mp[(size_t)i * NNODE] > 0) w |= (1u << i);
    int s0 = sw * 32;
    if (t >= s0 && t < s0 + 32) w |= (1u << (t - s0)); // self loop
    bits[(b * NNODE + t) * 32 + sw] = w;
}

// ---------------- generic strided batched GEMM ----------------
// C = alpha * A @ op(B) + bias ; op(B)=B^T if BT (B stored [Ncol,K]); ACT=1 -> relu
// M must be multiple of 64, K multiple of 16. Ncol guarded.
template<bool BT, int ACT>
__global__ void __launch_bounds__(256) gemm_k(
    int M, int Ncol, int K,
    const float* __restrict__ A, int lda, long long sA1, long long sA2,
    const float* __restrict__ B, int ldb, long long sB1, long long sB2,
    float* __restrict__ C, int ldc, long long sC1, long long sC2,
    const float* __restrict__ bias, float alpha, int bdiv)
{
    __shared__ float As[16][68];
    __shared__ float Bs[16][68];
    int bz = blockIdx.z;
    int i1 = bz / bdiv, i2 = bz - i1 * bdiv;
    A += i1 * sA1 + i2 * sA2;
    B += i1 * sB1 + i2 * sB2;
    C += i1 * sC1 + i2 * sC2;
    int m0 = blockIdx.y * 64;
    int n0 = blockIdx.x * 64;
    int tid = threadIdx.x;
    int tx = tid & 15, ty = tid >> 4;

    float acc[4][4];
    #pragma unroll
    for (int i = 0; i < 4; i++)
        #pragma unroll
        for (int j = 0; j < 4; j++) acc[i][j] = 0.f;

    for (int k0 = 0; k0 < K; k0 += 16) {
        { // A tile: [m0..m0+63] x [k0..k0+15]  -> As[k][m]
            int c = tid & 15, r0 = tid >> 4;
            #pragma unroll
            for (int p = 0; p < 4; p++) {
                int r = r0 + p * 16;
                As[c][r] = A[(size_t)(m0 + r) * lda + k0 + c];
            }
        }
        if (!BT) { // B[K,Ncol]
            int n = tid & 63, kk0 = tid >> 6;
            #pragma unroll
            for (int p = 0; p < 4; p++) {
                int kx = kk0 + p * 4;
                float v = (n0 + n < Ncol) ? B[(size_t)(k0 + kx) * ldb + n0 + n] : 0.f;
                Bs[kx][n] = v;
            }
        } else { // B[Ncol,K]
            int c = tid & 15, r0 = tid >> 4;
            #pragma unroll
            for (int p = 0; p < 4; p++) {
                int r = r0 + p * 16;
                float v = (n0 + r < Ncol) ? B[(size_t)(n0 + r) * ldb + k0 + c] : 0.f;
                Bs[c][r] = v;
            }
        }
        __syncthreads();
        #pragma unroll
        for (int kk = 0; kk < 16; kk++) {
            float av[4], bv[4];
            #pragma unroll
            for (int i = 0; i < 4; i++) av[i] = As[kk][ty * 4 + i];
            #pragma unroll
            for (int j = 0; j < 4; j++) bv[j] = Bs[kk][tx * 4 + j];
            #pragma unroll
            for (int i = 0; i < 4; i++)
                #pragma unroll
                for (int j = 0; j < 4; j++)
                    acc[i][j] += av[i] * bv[j];
        }
        __syncthreads();
    }
    #pragma unroll
    for (int i = 0; i < 4; i++) {
        int m = m0 + ty * 4 + i;
        #pragma unroll
        for (int j = 0; j < 4; j++) {
            int n = n0 + tx * 4 + j;
            if (n < Ncol) {
                float v = acc[i][j] * alpha;
                if (bias) v += bias[n];
                if (ACT == 1) v = fmaxf(v, 0.f);
                C[(size_t)m * ldc + n] = v;
            }
        }
    }
}

// ---------------- GAT a_src / a_dst: per (b,n) row, warp per head ----------------
__global__ void asad_k(const float* __restrict__ hb,
                       const float* __restrict__ attS, const float* __restrict__ attD,
                       float* __restrict__ as_, float* __restrict__ ad_)
{
    int row = blockIdx.x;            // b*N + n
    int w = threadIdx.x >> 5, lane = threadIdx.x & 31;
    const float* hp = hb + ((size_t)row * HH + w) * DD;
    const float* sp = attS + w * DD;
    const float* dp = attD + w * DD;
    float s = 0.f, d = 0.f;
    #pragma unroll
    for (int i = lane; i < DD; i += 32) {
        float hv = hp[i];
        s += hv * sp[i];
        d += hv * dp[i];
    }
    #pragma unroll
    for (int o = 16; o; o >>= 1) {
        s += __shfl_xor_sync(0xffffffffu, s, o);
        d += __shfl_xor_sync(0xffffffffu, d, o);
    }
    if (lane == 0) { as_[row * HH + w] = s; ad_[row * HH + w] = d; }
}

// ---------------- GAT alpha (rank-1 masked softmax row) ----------------
__global__ void gat_alpha_k(const float* __restrict__ as_, const float* __restrict__ ad_,
                            const unsigned* __restrict__ bits, float* __restrict__ sc)
{
    int t = blockIdx.x, h = blockIdx.y, b = blockIdx.z;
    __shared__ float sm[8];
    float adv = ad_[(b * NNODE + t) * HH + h];
    float* row = sc + ((size_t)(b * HH + h) * NNODE + t) * NNODE;
    const unsigned* bw = bits + (b * NNODE + t) * 32;
    float wv[4]; float sum = 0.f;
    #pragma unroll
    for (int j = 0; j < 4; j++) {
        int s = threadIdx.x + j * 256;
        float e = adv + as_[(b * NNODE + s) * HH + h];
        e = e >= 0.f ? e : 0.2f * e;
        unsigned m = (bw[s >> 5] >> (s & 31)) & 1u;
        float w = m ? __expf(e) : 0.f;
        wv[j] = w; sum += w;
    }
    sum = block_sum256(sum, sm);
    float inv = 1.f / sum;
    #pragma unroll
    for (int j = 0; j < 4; j++)
        row[threadIdx.x + j * 256] = wv[j] * inv;
}

// ---------------- transformer masked softmax (in-place on score rows) ----------------
__global__ void attn_softmax_k(float* __restrict__ sc, const unsigned* __restrict__ bits)
{
    int t = blockIdx.x, h = blockIdx.y, b = blockIdx.z;
    __shared__ float sm[8];
    float* row = sc + ((size_t)(b * HH + h) * NNODE + t) * NNODE;
    const unsigned* bw = bits + (b * NNODE + t) * 32;
    float wv[4]; float sum = 0.f;
    #pragma unroll
    for (int j = 0; j < 4; j++) {
        int s = threadIdx.x + j * 256;
        float v = row[s];
        unsigned m = (bw[s >> 5] >> (s & 31)) & 1u;
        float w = m ? __expf(v) : 0.f;
        wv[j] = w; sum += w;
    }
    sum = block_sum256(sum, sm);
    float inv = 1.f / sum;
    #pragma unroll
    for (int j = 0; j < 4; j++)
        row[threadIdx.x + j * 256] = wv[j] * inv;
}

// ---------------- mean over heads + bias ----------------
__global__ void headmean_k(const float* __restrict__ t2, const float* __restrict__ bias,
                           float* __restrict__ y)
{
    int idx = blockIdx.x * 256 + threadIdx.x;
    int c = idx & 255;
    size_t row = (size_t)(idx >> 8);
    float acc = 0.f;
    #pragma unroll
    for (int h = 0; h < HH; h++) acc += t2[(row * HH + h) * DD + c];
    y[idx] = acc * (1.f / HH) + bias[c];
}

// ---------------- layernorm: out = LN(a + (MODE? relu(bsrc) : bsrc)) ----------------
template<int MODE>
__global__ void ln_k(const float* __restrict__ a, const float* __restrict__ bsrc,
                     const float* __restrict__ gam, const float* __restrict__ bet,
                     float* __restrict__ out)
{
    __shared__ float sm[8];
    size_t row = blockIdx.x;
    int i = threadIdx.x;
    float v = a[row * DD + i];
    float w = bsrc[row * DD + i];
    if (MODE == 1) w = fmaxf(w, 0.f);
    v += w;
    float mean = block_sum256(v, sm) * (1.f / DD);
    float d = v - mean;
    float var = block_sum256(d * d, sm) * (1.f / DD);
    out[row * DD + i] = d * rsqrtf(var + 1e-5f) * gam[i] + bet[i];
}

// ---------------- host-side GEMM dispatch ----------------
static void gemm(bool bt, int act, int M, int Nc, int K,
                 const float* A, int lda, long long sA1, long long sA2,
                 const float* B, int ldb, long long sB1, long long sB2,
                 float* C, int ldc, long long sC1, long long sC2,
                 const float* bias, float alpha, int z, int bdiv)
{
    dim3 g((Nc + 63) / 64, (M + 63) / 64, z);
    if (!bt) {
        if (act) gemm_k<false,1><<<g,256>>>(M,Nc,K,A,lda,sA1,sA2,B,ldb,sB1,sB2,C,ldc,sC1,sC2,bias,alpha,bdiv);
        else     gemm_k<false,0><<<g,256>>>(M,Nc,K,A,lda,sA1,sA2,B,ldb,sB1,sB2,C,ldc,sC1,sC2,bias,alpha,bdiv);
    } else {
        if (act) gemm_k<true,1><<<g,256>>>(M,Nc,K,A,lda,sA1,sA2,B,ldb,sB1,sB2,C,ldc,sC1,sC2,bias,alpha,bdiv);
        else     gemm_k<true,0><<<g,256>>>(M,Nc,K,A,lda,sA1,sA2,B,ldb,sB1,sB2,C,ldc,sC1,sC2,bias,alpha,bdiv);
    }
}

extern "C" void kernel_launch(void* const* d_in, const int* in_sizes, int n_in,
                              void* d_out, int out_size)
{
    const float* emb  = (const float*)d_in[0];
    // d_in[1] rec_inp unused, d_in[3] dummy unused
    const int*   mask = (const int*)  d_in[2];
    const float* gatW = (const float*)d_in[4];
    const float* attS = (const float*)d_in[5];
    const float* attD = (const float*)d_in[6];
    const float* gatB = (const float*)d_in[7];
    const float* glnS = (const float*)d_in[8];
    const float* glnB = (const float*)d_in[9];
    const float* Wq = (const float*)d_in[10], *bq = (const float*)d_in[11];
    const float* Wk = (const float*)d_in[12], *bk = (const float*)d_in[13];
    const float* Wv = (const float*)d_in[14], *bv = (const float*)d_in[15];
    const float* Wo = (const float*)d_in[16], *bo = (const float*)d_in[17];
    const float* W1 = (const float*)d_in[18], *b1 = (const float*)d_in[19];
    const float* W2 = (const float*)d_in[20], *b2 = (const float*)d_in[21];
    const float* l1s = (const float*)d_in[22], *l1b = (const float*)d_in[23];
    const float* l2s = (const float*)d_in[24], *l2b = (const float*)d_in[25];
    float* out = (float*)d_out;

    float *XC,*HB,*T2,*AS,*AD,*SC,*Q,*Kb,*V,*AO,*Y,*FF; unsigned* BITS;
    cudaGetSymbolAddress((void**)&XC, g_XC);
    cudaGetSymbolAddress((void**)&HB, g_HB);
    cudaGetSymbolAddress((void**)&T2, g_T2);
    cudaGetSymbolAddress((void**)&AS, g_AS);
    cudaGetSymbolAddress((void**)&AD, g_AD);
    cudaGetSymbolAddress((void**)&SC, g_SC);
    cudaGetSymbolAddress((void**)&Q,  g_Q);
    cudaGetSymbolAddress((void**)&Kb, g_K);
    cudaGetSymbolAddress((void**)&V,  g_V);
    cudaGetSymbolAddress((void**)&AO, g_AO);
    cudaGetSymbolAddress((void**)&Y,  g_Y);
    cudaGetSymbolAddress((void**)&FF, g_FF);
    cudaGetSymbolAddress((void**)&BITS, g_BITS);

    const int M = BB * NNODE;                 // 8192
    const long long NHD = (long long)NNODE * HH * DD;
    const long long NN2 = (long long)NNODE * NNODE;
    const long long ND  = (long long)NNODE * DD;

    // ---- adjacency bitmask ----
    pack_adj_k<<<(BB*32*NNODE)/256, 256>>>(mask, BITS);

    // ---- GAT stack ----
    const float* x = emb;
    for (int l = 0; l < LGN; l++) {
        // h = x @ gatW[l]^T  -> [8192, H*D]
        gemm(true, 0, M, HH*DD, DD,
             x, DD, 0, 0,
             gatW + (size_t)l*HH*DD*DD, DD, 0, 0,
             HB, HH*DD, 0, 0, nullptr, 1.f, 1, 1);
        asad_k<<<M, 256>>>(HB, attS + l*HH*DD, attD + l*HH*DD, AS, AD);
        gat_alpha_k<<<dim3(NNODE, HH, BB), 256>>>(AS, AD, BITS, SC);
        // T2[b,:,h,:] = alpha[b,h] @ h[b,:,h,:]
        gemm(false, 0, NNODE, DD, NNODE,
             SC, NNODE, (long long)HH*NN2, NN2,
             HB, HH*DD, NHD, DD,
             T2, HH*DD, NHD, DD, nullptr, 1.f, BB*HH, HH);
        headmean_k<<<M, 256>>>(T2, gatB + l*DD, Y);
        x = Y;
    }
    // x = LN(emb + relu(Y))
    ln_k<1><<<M, 256>>>(emb, Y, glnS, glnB, XC);

    // ---- transformer layers ----
    const float scale = 0.17677669529663687f; // 1/sqrt(32)
    for (int l = 0; l < LTN; l++) {
        gemm(false, 0, M, DD, DD, XC, DD, 0,0, Wq + (size_t)l*DD*DD, DD, 0,0, Q,  DD, 0,0, bq + l*DD, 1.f, 1, 1);
        gemm(false, 0, M, DD, DD, XC, DD, 0,0, Wk + (size_t)l*DD*DD, DD, 0,0, Kb, DD, 0,0, bk + l*DD, 1.f, 1, 1);
        gemm(false, 0, M, DD, DD, XC, DD, 0,0, Wv + (size_t)l*DD*DD, DD, 0,0, V,  DD, 0,0, bv + l*DD, 1.f, 1, 1);
        // scores = scale * Q K^T per (b,h)
        gemm(true, 0, NNODE, NNODE, DHH,
             Q,  DD, ND, DHH,
             Kb, DD, ND, DHH,
             SC, NNODE, (long long)HH*NN2, NN2, nullptr, scale, BB*HH, HH);
        attn_softmax_k<<<dim3(NNODE, HH, BB), 256>>>(SC, BITS);
        // AO = attn @ V per (b,h)
        gemm(false, 0, NNODE, DHH, NNODE,
             SC, NNODE, (long long)HH*NN2, NN2,
             V,  DD, ND, DHH,
             AO, DD, ND, DHH, nullptr, 1.f, BB*HH, HH);
        gemm(false, 0, M, DD, DD, AO, DD, 0,0, Wo + (size_t)l*DD*DD, DD, 0,0, Y, DD, 0,0, bo + l*DD, 1.f, 1, 1);
        ln_k<0><<<M, 256>>>(XC, Y, l1s + l*DD, l1b + l*DD, XC);
        gemm(false, 1, M, DFFX, DD, XC, DD, 0,0, W1 + (size_t)l*DD*DFFX, DFFX, 0,0, FF, DFFX, 0,0, b1 + l*DFFX, 1.f, 1, 1);
        gemm(false, 0, M, DD, DFFX, FF, DFFX, 0,0, W2 + (size_t)l*DFFX*DD, DD, 0,0, Y, DD, 0,0, b2 + l*DD, 1.f, 1, 1);
        float* dst = (l == LTN - 1) ? out : XC;
        ln_k<0><<<M, 256>>>(XC, Y, l2s + l*DD, l2b + l*DD, dst);
    }
}

// round 2
// speedup vs baseline: 2.5098x; 2.5098x over previous
#include <cuda_runtime.h>
#include <math.h>

// ---------------- dims ----------------
#define BB    8
#define NNODE 1024
#define DD    256
#define HH    8
#define DHH   32
#define DFFX  1024
#define LGN   2
#define LTN   2
#define NBCAP 256

// ---------------- scratch (device globals; no runtime allocation) ----------------
__device__ float    g_XC[BB*NNODE*DD];          // current x
__device__ float    g_HB[BB*NNODE*HH*DD];       // GAT per-head features h [b,n,h,c]
__device__ float    g_AS[BB*NNODE*HH];
__device__ float    g_AD[BB*NNODE*HH];
__device__ float    g_Q [BB*NNODE*DD];
__device__ float    g_K [BB*NNODE*DD];
__device__ float    g_V [BB*NNODE*DD];
__device__ float    g_AO[BB*NNODE*DD];
__device__ float    g_Y [BB*NNODE*DD];
__device__ float    g_FF[BB*NNODE*DFFX];
__device__ unsigned g_BITS[BB*NNODE*(NNODE/32)]; // adjacency A_ts packed over s
__device__ int      g_NBR[BB*NNODE*NBCAP];       // in-neighbor lists per (b,t)
__device__ int      g_CNT[BB*NNODE];

// ---------------- helpers ----------------
__device__ __forceinline__ float block_sum256(float v, float* sm) {
    #pragma unroll
    for (int o = 16; o; o >>= 1) v += __shfl_xor_sync(0xffffffffu, v, o);
    int w = threadIdx.x >> 5;
    if ((threadIdx.x & 31) == 0) sm[w] = v;
    __syncthreads();
    if (threadIdx.x < 8) {
        v = sm[threadIdx.x];
        #pragma unroll
        for (int o = 4; o; o >>= 1) v += __shfl_xor_sync(0xffu, v, o);
        if (threadIdx.x == 0) sm[0] = v;
    }
    __syncthreads();
    v = sm[0];
    __syncthreads();
    return v;
}

// ---------------- adjacency pack: bits[b][t][s/32] ----------------
__global__ void pack_adj_k(const int* __restrict__ mask, unsigned* __restrict__ bits) {
    int idx = blockIdx.x * blockDim.x + threadIdx.x; // B*32*N threads
    int t  = idx & (NNODE - 1);
    int sw = (idx >> 10) & 31;
    int b  = idx >> 15;
    const int* mp = mask + ((size_t)b * NNODE + (size_t)sw * 32) * NNODE + t;
    unsigned w = 0;
    #pragma unroll
    for (int i = 0; i < 32; i++)
        if (mp[(size_t)i * NNODE] > 0) w |= (1u << i);
    int s0 = sw * 32;
    if (t >= s0 && t < s0 + 32) w |= (1u << (t - s0)); // self loop
    bits[(b * NNODE + t) * 32 + sw] = w;
}

// ---------------- neighbor list build ----------------
__global__ void build_nbr_k(const unsigned* __restrict__ bits,
                            int* __restrict__ nbr, int* __restrict__ cnt) {
    int bt = blockIdx.x * blockDim.x + threadIdx.x;
    if (bt >= BB * NNODE) return;
    const unsigned* bw = bits + (size_t)bt * 32;
    int* np = nbr + (size_t)bt * NBCAP;
    int c = 0;
    #pragma unroll 4
    for (int w = 0; w < 32; w++) {
        unsigned m = bw[w];
        while (m) {
            int bit = __ffs(m) - 1;
            m &= m - 1;
            if (c < NBCAP) np[c] = w * 32 + bit;
            c++;
        }
    }
    cnt[bt] = c < NBCAP ? c : NBCAP;
}

// ---------------- generic strided batched GEMM (SIMT fp32) ----------------
template<bool BT, int ACT>
__global__ void __launch_bounds__(256) gemm_k(
    int M, int Ncol, int K,
    const float* __restrict__ A, int lda,
    const float* __restrict__ B, int ldb,
    float* __restrict__ C, int ldc,
    const float* __restrict__ bias, float alpha)
{
    __shared__ float As[16][68];
    __shared__ float Bs[16][68];
    int m0 = blockIdx.y * 64;
    int n0 = blockIdx.x * 64;
    int tid = threadIdx.x;
    int tx = tid & 15, ty = tid >> 4;

    float acc[4][4];
    #pragma unroll
    for (int i = 0; i < 4; i++)
        #pragma unroll
        for (int j = 0; j < 4; j++) acc[i][j] = 0.f;

    for (int k0 = 0; k0 < K; k0 += 16) {
        {
            int c = tid & 15, r0 = tid >> 4;
            #pragma unroll
            for (int p = 0; p < 4; p++) {
                int r = r0 + p * 16;
                As[c][r] = A[(size_t)(m0 + r) * lda + k0 + c];
            }
        }
        if (!BT) {
            int n = tid & 63, kk0 = tid >> 6;
            #pragma unroll
            for (int p = 0; p < 4; p++) {
                int kx = kk0 + p * 4;
                float v = (n0 + n < Ncol) ? B[(size_t)(k0 + kx) * ldb + n0 + n] : 0.f;
                Bs[kx][n] = v;
            }
        } else {
            int c = tid & 15, r0 = tid >> 4;
            #pragma unroll
            for (int p = 0; p < 4; p++) {
                int r = r0 + p * 16;
                float v = (n0 + r < Ncol) ? B[(size_t)(n0 + r) * ldb + k0 + c] : 0.f;
                Bs[c][r] = v;
            }
        }
        __syncthreads();
        #pragma unroll
        for (int kk = 0; kk < 16; kk++) {
            float av[4], bv[4];
            #pragma unroll
            for (int i = 0; i < 4; i++) av[i] = As[kk][ty * 4 + i];
            #pragma unroll
            for (int j = 0; j < 4; j++) bv[j] = Bs[kk][tx * 4 + j];
            #pragma unroll
            for (int i = 0; i < 4; i++)
                #pragma unroll
                for (int j = 0; j < 4; j++)
                    acc[i][j] += av[i] * bv[j];
        }
        __syncthreads();
    }
    #pragma unroll
    for (int i = 0; i < 4; i++) {
        int m = m0 + ty * 4 + i;
        #pragma unroll
        for (int j = 0; j < 4; j++) {
            int n = n0 + tx * 4 + j;
            if (n < Ncol) {
                float v = acc[i][j] * alpha;
                if (bias) v += bias[n];
                if (ACT == 1) v = fmaxf(v, 0.f);
                C[(size_t)m * ldc + n] = v;
            }
        }
    }
}

// ---------------- GAT a_src / a_dst ----------------
__global__ void asad_k(const float* __restrict__ hb,
                       const float* __restrict__ attS, const float* __restrict__ attD,
                       float* __restrict__ as_, float* __restrict__ ad_)
{
    int row = blockIdx.x;            // b*N + n
    int w = threadIdx.x >> 5, lane = threadIdx.x & 31;
    const float* hp = hb + ((size_t)row * HH + w) * DD;
    const float* sp = attS + w * DD;
    const float* dp = attD + w * DD;
    float s = 0.f, d = 0.f;
    #pragma unroll
    for (int i = lane; i < DD; i += 32) {
        float hv = hp[i];
        s += hv * sp[i];
        d += hv * dp[i];
    }
    #pragma unroll
    for (int o = 16; o; o >>= 1) {
        s += __shfl_xor_sync(0xffffffffu, s, o);
        d += __shfl_xor_sync(0xffffffffu, d, o);
    }
    if (lane == 0) { as_[row * HH + w] = s; ad_[row * HH + w] = d; }
}

// ---------------- sparse GAT aggregation (alpha + agg + head-mean + bias fused) ----------------
__global__ void __launch_bounds__(256) gat_agg_k(
    const float* __restrict__ hb, const float* __restrict__ as_,
    const float* __restrict__ ad_, const int* __restrict__ nbr,
    const int* __restrict__ cnt, const float* __restrict__ bias,
    float* __restrict__ y)
{
    __shared__ int   s_nbr[NBCAP];
    __shared__ float s_alpha[HH][NBCAP];
    __shared__ float s_inv[HH];
    __shared__ float4 s_red[4][64];
    int bt  = blockIdx.x;
    int b   = bt >> 10;
    int tid = threadIdx.x;
    int nc  = cnt[bt];
    for (int j = tid; j < nc; j += 256) s_nbr[j] = nbr[(size_t)bt * NBCAP + j];
    __syncthreads();

    // stage A: unnormalized weights
    for (int j = tid; j < nc; j += 256) {
        int s = s_nbr[j];
        const float* ap = as_ + (size_t)(b * NNODE + s) * HH;
        #pragma unroll
        for (int h = 0; h < HH; h++) {
            float e = ad_[bt * HH + h] + ap[h];
            e = e >= 0.f ? e : 0.2f * e;
            s_alpha[h][j] = __expf(e);
        }
    }
    __syncthreads();

    // per-head sums -> 1/(8*sum)
    int wid = tid >> 5, lane = tid & 31;
    {
        float sum = 0.f;
        for (int j = lane; j < nc; j += 32) sum += s_alpha[wid][j];
        #pragma unroll
        for (int o = 16; o; o >>= 1) sum += __shfl_xor_sync(0xffffffffu, sum, o);
        if (lane == 0) s_inv[wid] = 1.f / (8.f * sum);
    }
    __syncthreads();
    for (int j = tid; j < nc; j += 256) {
        #pragma unroll
        for (int h = 0; h < HH; h++) s_alpha[h][j] *= s_inv[h];
    }
    __syncthreads();

    // stage B: thread handles heads {h0,h0+1}, columns c4..c4+3
    int hp = tid >> 6;          // 0..3
    int h0 = hp * 2;
    int cg = tid & 63;
    int c4 = cg * 4;
    float a0x = 0.f, a1x = 0.f, a2x = 0.f, a3x = 0.f;
    for (int j = 0; j < nc; j++) {
        int s = s_nbr[j];
        const float* base = hb + (size_t)(b * NNODE + s) * (HH * DD);
        float w0 = s_alpha[h0][j], w1 = s_alpha[h0 + 1][j];
        float4 v0 = *(const float4*)(base + h0 * DD + c4);
        float4 v1 = *(const float4*)(base + (h0 + 1) * DD + c4);
        a0x = fmaf(w0, v0.x, fmaf(w1, v1.x, a0x));
        a1x = fmaf(w0, v0.y, fmaf(w1, v1.y, a1x));
        a2x = fmaf(w0, v0.z, fmaf(w1, v1.z, a2x));
        a3x = fmaf(w0, v0.w, fmaf(w1, v1.w, a3x));
    }
    s_red[hp][cg] = make_float4(a0x, a1x, a2x, a3x);
    __syncthreads();
    {
        int c = tid;
        const float* r0 = (const float*)&s_red[0][c >> 2];
        const float* r1 = (const float*)&s_red[1][c >> 2];
        const float* r2 = (const float*)&s_red[2][c >> 2];
        const float* r3 = (const float*)&s_red[3][c >> 2];
        int u = c & 3;
        y[(size_t)bt * DD + c] = r0[u] + r1[u] + r2[u] + r3[u] + bias[c];
    }
}

// ---------------- sparse masked attention (scores+softmax+AV fused) ----------------
__global__ void __launch_bounds__(256) attn_sparse_k(
    const float* __restrict__ Qm, const float* __restrict__ Km,
    const float* __restrict__ Vm, const int* __restrict__ nbr,
    const int* __restrict__ cnt, float* __restrict__ Om)
{
    __shared__ int s_nbr[NBCAP];
    int bt  = blockIdx.x;
    int b   = bt >> 10;
    int tid = threadIdx.x;
    int nc  = cnt[bt];
    for (int j = tid; j < nc; j += 256) s_nbr[j] = nbr[(size_t)bt * NBCAP + j];
    __syncthreads();
    int h = tid >> 5, lane = tid & 31;
    float q = Qm[(size_t)bt * DD + h * DHH + lane] * 0.17677669529663687f;
    float accv = 0.f, accw = 0.f;
    int j = 0;
    for (; j + 4 <= nc; j += 4) {
        float d[4], vv[4];
        #pragma unroll
        for (int u = 0; u < 4; u++) {
            int s = s_nbr[j + u];
            size_t base = (size_t)(b * NNODE + s) * DD + h * DHH + lane;
            d[u]  = q * Km[base];
            vv[u] = Vm[base];
        }
        #pragma unroll
        for (int o = 16; o; o >>= 1) {
            #pragma unroll
            for (int u = 0; u < 4; u++) d[u] += __shfl_xor_sync(0xffffffffu, d[u], o);
        }
        #pragma unroll
        for (int u = 0; u < 4; u++) {
            float w = __expf(d[u]);
            accv = fmaf(w, vv[u], accv);
            accw += w;
        }
    }
    for (; j < nc; j++) {
        int s = s_nbr[j];
        size_t base = (size_t)(b * NNODE + s) * DD + h * DHH + lane;
        float d = q * Km[base];
        float vvv = Vm[base];
        #pragma unroll
        for (int o = 16; o; o >>= 1) d += __shfl_xor_sync(0xffffffffu, d, o);
        float w = __expf(d);
        accv = fmaf(w, vvv, accv);
        accw += w;
    }
    Om[(size_t)bt * DD + h * DHH + lane] = accv / accw;
}

// ---------------- layernorm: out = LN(a + (MODE? relu(bsrc) : bsrc)) ----------------
template<int MODE>
__global__ void ln_k(const float* __restrict__ a, const float* __restrict__ bsrc,
                     const float* __restrict__ gam, const float* __restrict__ bet,
                     float* __restrict__ out)
{
    __shared__ float sm[8];
    size_t row = blockIdx.x;
    int i = threadIdx.x;
    float v = a[row * DD + i];
    float w = bsrc[row * DD + i];
    if (MODE == 1) w = fmaxf(w, 0.f);
    v += w;
    float mean = block_sum256(v, sm) * (1.f / DD);
    float d = v - mean;
    float var = block_sum256(d * d, sm) * (1.f / DD);
    out[row * DD + i] = d * rsqrtf(var + 1e-5f) * gam[i] + bet[i];
}

// ---------------- host-side GEMM dispatch ----------------
static void gemm(bool bt, int act, int M, int Nc, int K,
                 const float* A, int lda, const float* B, int ldb,
                 float* C, int ldc, const float* bias, float alpha)
{
    dim3 g((Nc + 63) / 64, (M + 63) / 64, 1);
    if (!bt) {
        if (act) gemm_k<false,1><<<g,256>>>(M,Nc,K,A,lda,B,ldb,C,ldc,bias,alpha);
        else     gemm_k<false,0><<<g,256>>>(M,Nc,K,A,lda,B,ldb,C,ldc,bias,alpha);
    } else {
        if (act) gemm_k<true,1><<<g,256>>>(M,Nc,K,A,lda,B,ldb,C,ldc,bias,alpha);
        else     gemm_k<true,0><<<g,256>>>(M,Nc,K,A,lda,B,ldb,C,ldc,bias,alpha);
    }
}

extern "C" void kernel_launch(void* const* d_in, const int* in_sizes, int n_in,
                              void* d_out, int out_size)
{
    const float* emb  = (const float*)d_in[0];
    const int*   mask = (const int*)  d_in[2];
    const float* gatW = (const float*)d_in[4];
    const float* attS = (const float*)d_in[5];
    const float* attD = (const float*)d_in[6];
    const float* gatB = (const float*)d_in[7];
    const float* glnS = (const float*)d_in[8];
    const float* glnB = (const float*)d_in[9];
    const float* Wq = (const float*)d_in[10], *bq = (const float*)d_in[11];
    const float* Wk = (const float*)d_in[12], *bk = (const float*)d_in[13];
    const float* Wv = (const float*)d_in[14], *bv = (const float*)d_in[15];
    const float* Wo = (const float*)d_in[16], *bo = (const float*)d_in[17];
    const float* W1 = (const float*)d_in[18], *b1 = (const float*)d_in[19];
    const float* W2 = (const float*)d_in[20], *b2 = (const float*)d_in[21];
    const float* l1s = (const float*)d_in[22], *l1b = (const float*)d_in[23];
    const float* l2s = (const float*)d_in[24], *l2b = (const float*)d_in[25];
    float* out = (float*)d_out;

    float *XC,*HB,*AS,*AD,*Q,*Kb,*V,*AO,*Y,*FF; unsigned* BITS; int *NBR,*CNT;
    cudaGetSymbolAddress((void**)&XC, g_XC);
    cudaGetSymbolAddress((void**)&HB, g_HB);
    cudaGetSymbolAddress((void**)&AS, g_AS);
    cudaGetSymbolAddress((void**)&AD, g_AD);
    cudaGetSymbolAddress((void**)&Q,  g_Q);
    cudaGetSymbolAddress((void**)&Kb, g_K);
    cudaGetSymbolAddress((void**)&V,  g_V);
    cudaGetSymbolAddress((void**)&AO, g_AO);
    cudaGetSymbolAddress((void**)&Y,  g_Y);
    cudaGetSymbolAddress((void**)&FF, g_FF);
    cudaGetSymbolAddress((void**)&BITS, g_BITS);
    cudaGetSymbolAddress((void**)&NBR, g_NBR);
    cudaGetSymbolAddress((void**)&CNT, g_CNT);

    const int M = BB * NNODE;                 // 8192

    // ---- adjacency: bitmask + neighbor lists ----
    pack_adj_k<<<(BB*32*NNODE)/256, 256>>>(mask, BITS);
    build_nbr_k<<<(BB*NNODE)/256, 256>>>(BITS, NBR, CNT);

    // ---- GAT stack ----
    const float* x = emb;
    for (int l = 0; l < LGN; l++) {
        // h = x @ gatW[l]^T  -> [8192, H*D]
        gemm(true, 0, M, HH*DD, DD,
             x, DD, gatW + (size_t)l*HH*DD*DD, DD,
             HB, HH*DD, nullptr, 1.f);
        asad_k<<<M, 256>>>(HB, attS + l*HH*DD, attD + l*HH*DD, AS, AD);
        gat_agg_k<<<M, 256>>>(HB, AS, AD, NBR, CNT, gatB + l*DD, Y);
        x = Y;
    }
    // x = LN(emb + relu(Y))
    ln_k<1><<<M, 256>>>(emb, Y, glnS, glnB, XC);

    // ---- transformer layers ----
    for (int l = 0; l < LTN; l++) {
        gemm(false, 0, M, DD, DD, XC, DD, Wq + (size_t)l*DD*DD, DD, Q,  DD, bq + l*DD, 1.f);
        gemm(false, 0, M, DD, DD, XC, DD, Wk + (size_t)l*DD*DD, DD, Kb, DD, bk + l*DD, 1.f);
        gemm(false, 0, M, DD, DD, XC, DD, Wv + (size_t)l*DD*DD, DD, V,  DD, bv + l*DD, 1.f);
        attn_sparse_k<<<M, 256>>>(Q, Kb, V, NBR, CNT, AO);
        gemm(false, 0, M, DD, DD, AO, DD, Wo + (size_t)l*DD*DD, DD, Y, DD, bo + l*DD, 1.f);
        ln_k<0><<<M, 256>>>(XC, Y, l1s + l*DD, l1b + l*DD, XC);
        gemm(false, 1, M, DFFX, DD, XC, DD, W1 + (size_t)l*DD*DFFX, DFFX, FF, DFFX, b1 + l*DFFX, 1.f);
        gemm(false, 0, M, DD, DFFX, FF, DFFX, W2 + (size_t)l*DFFX*DD, DD, Y, DD, b2 + l*DD, 1.f);
        float* dst = (l == LTN - 1) ? out : XC;
        ln_k<0><<<M, 256>>>(XC, Y, l2s + l*DD, l2b + l*DD, dst);
    }
}

// round 3
// speedup vs baseline: 2.7697x; 1.1036x over previous
#include <cuda_runtime.h>
#include <math.h>

// ---------------- dims ----------------
#define BB    8
#define NNODE 1024
#define DD    256
#define HH    8
#define DHH   32
#define DFFX  1024
#define LGN   2
#define LTN   2
#define NBCAP 256

// ---------------- scratch (device globals; no runtime allocation) ----------------
__device__ float    g_XC[BB*NNODE*DD];
__device__ float    g_HB[BB*NNODE*HH*DD];
__device__ float    g_AS[BB*NNODE*HH];
__device__ float    g_AD[BB*NNODE*HH];
__device__ float    g_Q [BB*NNODE*DD];
__device__ float    g_K [BB*NNODE*DD];
__device__ float    g_V [BB*NNODE*DD];
__device__ float    g_AO[BB*NNODE*DD];
__device__ float    g_Y [BB*NNODE*DD];
__device__ float    g_FF[BB*NNODE*DFFX];
__device__ unsigned g_BITS[BB*NNODE*(NNODE/32)];
__device__ int      g_NBR[BB*NNODE*NBCAP];
__device__ int      g_CNT[BB*NNODE];

// ---------------- helpers ----------------
__device__ __forceinline__ float block_sum256(float v, float* sm) {
    #pragma unroll
    for (int o = 16; o; o >>= 1) v += __shfl_xor_sync(0xffffffffu, v, o);
    int w = threadIdx.x >> 5;
    if ((threadIdx.x & 31) == 0) sm[w] = v;
    __syncthreads();
    if (threadIdx.x < 8) {
        v = sm[threadIdx.x];
        #pragma unroll
        for (int o = 4; o; o >>= 1) v += __shfl_xor_sync(0xffu, v, o);
        if (threadIdx.x == 0) sm[0] = v;
    }
    __syncthreads();
    v = sm[0];
    __syncthreads();
    return v;
}

__device__ __forceinline__ unsigned f2tf(float x) {
    unsigned r;
    asm("cvt.rna.tf32.f32 %0, %1;" : "=r"(r) : "f"(x));
    return r;
}

__device__ __forceinline__ void mma_tf32(float* c, const unsigned* a, const unsigned* b) {
    asm volatile(
        "mma.sync.aligned.m16n8k8.row.col.f32.tf32.tf32.f32 "
        "{%0,%1,%2,%3}, {%4,%5,%6,%7}, {%8,%9}, {%0,%1,%2,%3};\n"
        : "+f"(c[0]), "+f"(c[1]), "+f"(c[2]), "+f"(c[3])
        : "r"(a[0]), "r"(a[1]), "r"(a[2]), "r"(a[3]), "r"(b[0]), "r"(b[1]));
}

// ---------------- adjacency pack: bits[b][t][s/32] ----------------
__global__ void pack_adj_k(const int* __restrict__ mask, unsigned* __restrict__ bits) {
    int idx = blockIdx.x * blockDim.x + threadIdx.x;
    int t  = idx & (NNODE - 1);
    int sw = (idx >> 10) & 31;
    int b  = idx >> 15;
    const int* mp = mask + ((size_t)b * NNODE + (size_t)sw * 32) * NNODE + t;
    unsigned w = 0;
    #pragma unroll
    for (int i = 0; i < 32; i++)
        if (mp[(size_t)i * NNODE] > 0) w |= (1u << i);
    int s0 = sw * 32;
    if (t >= s0 && t < s0 + 32) w |= (1u << (t - s0));
    bits[(b * NNODE + t) * 32 + sw] = w;
}

// ---------------- neighbor list build ----------------
__global__ void build_nbr_k(const unsigned* __restrict__ bits,
                            int* __restrict__ nbr, int* __restrict__ cnt) {
    int bt = blockIdx.x * blockDim.x + threadIdx.x;
    if (bt >= BB * NNODE) return;
    const unsigned* bw = bits + (size_t)bt * 32;
    int* np = nbr + (size_t)bt * NBCAP;
    int c = 0;
    #pragma unroll 4
    for (int w = 0; w < 32; w++) {
        unsigned m = bw[w];
        while (m) {
            int bit = __ffs(m) - 1;
            m &= m - 1;
            if (c < NBCAP) np[c] = w * 32 + bit;
            c++;
        }
    }
    cnt[bt] = c < NBCAP ? c : NBCAP;
}

// ---------------- TF32 tensor-core GEMM ----------------
// C[M,N] = A[M,K] @ op(B) (+bias)(relu if ACT). op(B)=B^T if BT (B stored [N,K]).
// Requires: M%128==0, N%128==0, K%16==0, 16B-aligned rows.
template<bool BT, int ACT>
__global__ void __launch_bounds__(256) mma_gemm_k(
    int M, int Ncol, int K,
    const float* __restrict__ A, int lda,
    const float* __restrict__ B, int ldb,
    float* __restrict__ C, int ldc,
    const float* __restrict__ bias)
{
    __shared__ float As[16][136];
    __shared__ float Bs[16][136];
    const int tid  = threadIdx.x;
    const int lane = tid & 31, wid = tid >> 5;
    const int wm = wid & 3, wn = wid >> 2;      // 4 x 2 warp grid
    const int m0 = blockIdx.y * 128, n0 = blockIdx.x * 128;
    const int r = lane >> 2, cq = lane & 3;

    float acc[2][8][4];
    #pragma unroll
    for (int mt = 0; mt < 2; mt++)
        #pragma unroll
        for (int nt = 0; nt < 8; nt++)
            #pragma unroll
            for (int u = 0; u < 4; u++) acc[mt][nt][u] = 0.f;

    const int arow = tid >> 2;   // 0..63
    const int aqc  = tid & 3;

    for (int k0 = 0; k0 < K; k0 += 16) {
        // ---- A tile 128x16 -> As[k][m] (transposed, qc-rotated STS) ----
        #pragma unroll
        for (int p = 0; p < 2; p++) {
            int rr = arow + p * 64;
            float4 v = *(const float4*)(A + (size_t)(m0 + rr) * lda + k0 + aqc * 4);
            float e[4] = {v.x, v.y, v.z, v.w};
            #pragma unroll
            for (int u = 0; u < 4; u++) {
                int j = (u + aqc) & 3;
                As[aqc * 4 + j][rr] = __uint_as_float(f2tf(e[j]));
            }
        }
        // ---- B tile -> Bs[k][n] ----
        if (!BT) {
            int kr = tid >> 5;      // 0..7
            int cc = tid & 31;
            #pragma unroll
            for (int p = 0; p < 2; p++) {
                int kk = kr + p * 8;
                float4 v = *(const float4*)(B + (size_t)(k0 + kk) * ldb + n0 + cc * 4);
                Bs[kk][cc * 4 + 0] = __uint_as_float(f2tf(v.x));
                Bs[kk][cc * 4 + 1] = __uint_as_float(f2tf(v.y));
                Bs[kk][cc * 4 + 2] = __uint_as_float(f2tf(v.z));
                Bs[kk][cc * 4 + 3] = __uint_as_float(f2tf(v.w));
            }
        } else {
            #pragma unroll
            for (int p = 0; p < 2; p++) {
                int rr = arow + p * 64;
                float4 v = *(const float4*)(B + (size_t)(n0 + rr) * ldb + k0 + aqc * 4);
                float e[4] = {v.x, v.y, v.z, v.w};
                #pragma unroll
                for (int u = 0; u < 4; u++) {
                    int j = (u + aqc) & 3;
                    Bs[aqc * 4 + j][rr] = __uint_as_float(f2tf(e[j]));
                }
            }
        }
        __syncthreads();

        #pragma unroll
        for (int ks = 0; ks < 2; ks++) {
            const int kb = ks * 8;
            unsigned af[2][4], bf[8][2];
            #pragma unroll
            for (int mt = 0; mt < 2; mt++) {
                int mrow = wm * 32 + mt * 16;
                af[mt][0] = __float_as_uint(As[kb + cq    ][mrow + r]);
                af[mt][1] = __float_as_uint(As[kb + cq    ][mrow + r + 8]);
                af[mt][2] = __float_as_uint(As[kb + cq + 4][mrow + r]);
                af[mt][3] = __float_as_uint(As[kb + cq + 4][mrow + r + 8]);
            }
            #pragma unroll
            for (int nt = 0; nt < 8; nt++) {
                int nn = wn * 64 + nt * 8 + r;
                bf[nt][0] = __float_as_uint(Bs[kb + cq    ][nn]);
                bf[nt][1] = __float_as_uint(Bs[kb + cq + 4][nn]);
            }
            #pragma unroll
            for (int mt = 0; mt < 2; mt++)
                #pragma unroll
                for (int nt = 0; nt < 8; nt++)
                    mma_tf32(acc[mt][nt], af[mt], bf[nt]);
        }
        __syncthreads();
    }

    // ---- epilogue ----
    #pragma unroll
    for (int mt = 0; mt < 2; mt++) {
        int mrow = m0 + wm * 32 + mt * 16 + r;
        #pragma unroll
        for (int nt = 0; nt < 8; nt++) {
            int ncol = n0 + wn * 64 + nt * 8 + cq * 2;
            float* ac = acc[mt][nt];
            float2 v0 = make_float2(ac[0], ac[1]);
            float2 v1 = make_float2(ac[2], ac[3]);
            if (bias) {
                float b0 = bias[ncol], b1 = bias[ncol + 1];
                v0.x += b0; v0.y += b1; v1.x += b0; v1.y += b1;
            }
            if (ACT == 1) {
                v0.x = fmaxf(v0.x, 0.f); v0.y = fmaxf(v0.y, 0.f);
                v1.x = fmaxf(v1.x, 0.f); v1.y = fmaxf(v1.y, 0.f);
            }
            *(float2*)(C + (size_t)mrow * ldc + ncol) = v0;
            *(float2*)(C + (size_t)(mrow + 8) * ldc + ncol) = v1;
        }
    }
}

// ---------------- GAT a_src / a_dst ----------------
__global__ void asad_k(const float* __restrict__ hb,
                       const float* __restrict__ attS, const float* __restrict__ attD,
                       float* __restrict__ as_, float* __restrict__ ad_)
{
    int row = blockIdx.x;
    int w = threadIdx.x >> 5, lane = threadIdx.x & 31;
    const float* hp = hb + ((size_t)row * HH + w) * DD;
    const float* sp = attS + w * DD;
    const float* dp = attD + w * DD;
    float s = 0.f, d = 0.f;
    #pragma unroll
    for (int i = lane; i < DD; i += 32) {
        float hv = hp[i];
        s += hv * sp[i];
        d += hv * dp[i];
    }
    #pragma unroll
    for (int o = 16; o; o >>= 1) {
        s += __shfl_xor_sync(0xffffffffu, s, o);
        d += __shfl_xor_sync(0xffffffffu, d, o);
    }
    if (lane == 0) { as_[row * HH + w] = s; ad_[row * HH + w] = d; }
}

// ---------------- sparse GAT aggregation ----------------
__global__ void __launch_bounds__(256) gat_agg_k(
    const float* __restrict__ hb, const float* __restrict__ as_,
    const float* __restrict__ ad_, const int* __restrict__ nbr,
    const int* __restrict__ cnt, const float* __restrict__ bias,
    float* __restrict__ y)
{
    __shared__ int   s_nbr[NBCAP];
    __shared__ float s_alpha[HH][NBCAP];
    __shared__ float s_inv[HH];
    __shared__ float4 s_red[4][64];
    int bt  = blockIdx.x;
    int b   = bt >> 10;
    int tid = threadIdx.x;
    int nc  = cnt[bt];
    for (int j = tid; j < nc; j += 256) s_nbr[j] = nbr[(size_t)bt * NBCAP + j];
    __syncthreads();

    for (int j = tid; j < nc; j += 256) {
        int s = s_nbr[j];
        const float* ap = as_ + (size_t)(b * NNODE + s) * HH;
        #pragma unroll
        for (int h = 0; h < HH; h++) {
            float e = ad_[bt * HH + h] + ap[h];
            e = e >= 0.f ? e : 0.2f * e;
            s_alpha[h][j] = __expf(e);
        }
    }
    __syncthreads();

    int wid = tid >> 5, lane = tid & 31;
    {
        float sum = 0.f;
        for (int j = lane; j < nc; j += 32) sum += s_alpha[wid][j];
        #pragma unroll
        for (int o = 16; o; o >>= 1) sum += __shfl_xor_sync(0xffffffffu, sum, o);
        if (lane == 0) s_inv[wid] = 1.f / (8.f * sum);
    }
    __syncthreads();
    for (int j = tid; j < nc; j += 256) {
        #pragma unroll
        for (int h = 0; h < HH; h++) s_alpha[h][j] *= s_inv[h];
    }
    __syncthreads();

    int hp = tid >> 6;
    int h0 = hp * 2;
    int cg = tid & 63;
    int c4 = cg * 4;
    float a0x = 0.f, a1x = 0.f, a2x = 0.f, a3x = 0.f;
    for (int j = 0; j < nc; j++) {
        int s = s_nbr[j];
        const float* base = hb + (size_t)(b * NNODE + s) * (HH * DD);
        float w0 = s_alpha[h0][j], w1 = s_alpha[h0 + 1][j];
        float4 v0 = *(const float4*)(base + h0 * DD + c4);
        float4 v1 = *(const float4*)(base + (h0 + 1) * DD + c4);
        a0x = fmaf(w0, v0.x, fmaf(w1, v1.x, a0x));
        a1x = fmaf(w0, v0.y, fmaf(w1, v1.y, a1x));
        a2x = fmaf(w0, v0.z, fmaf(w1, v1.z, a2x));
        a3x = fmaf(w0, v0.w, fmaf(w1, v1.w, a3x));
    }
    s_red[hp][cg] = make_float4(a0x, a1x, a2x, a3x);
    __syncthreads();
    {
        int c = tid;
        const float* r0 = (const float*)&s_red[0][c >> 2];
        const float* r1 = (const float*)&s_red[1][c >> 2];
        const float* r2 = (const float*)&s_red[2][c >> 2];
        const float* r3 = (const float*)&s_red[3][c >> 2];
        int u = c & 3;
        y[(size_t)bt * DD + c] = r0[u] + r1[u] + r2[u] + r3[u] + bias[c];
    }
}

// ---------------- sparse masked attention ----------------
__global__ void __launch_bounds__(256) attn_sparse_k(
    const float* __restrict__ Qm, const float* __restrict__ Km,
    const float* __restrict__ Vm, const int* __restrict__ nbr,
    const int* __restrict__ cnt, float* __restrict__ Om)
{
    __shared__ int s_nbr[NBCAP];
    int bt  = blockIdx.x;
    int b   = bt >> 10;
    int tid = threadIdx.x;
    int nc  = cnt[bt];
    for (int j = tid; j < nc; j += 256) s_nbr[j] = nbr[(size_t)bt * NBCAP + j];
    __syncthreads();
    int h = tid >> 5, lane = tid & 31;
    float q = Qm[(size_t)bt * DD + h * DHH + lane] * 0.17677669529663687f;
    float accv = 0.f, accw = 0.f;
    int j = 0;
    for (; j + 4 <= nc; j += 4) {
        float d[4], vv[4];
        #pragma unroll
        for (int u = 0; u < 4; u++) {
            int s = s_nbr[j + u];
            size_t base = (size_t)(b * NNODE + s) * DD + h * DHH + lane;
            d[u]  = q * Km[base];
            vv[u] = Vm[base];
        }
        #pragma unroll
        for (int o = 16; o; o >>= 1) {
            #pragma unroll
            for (int u = 0; u < 4; u++) d[u] += __shfl_xor_sync(0xffffffffu, d[u], o);
        }
        #pragma unroll
        for (int u = 0; u < 4; u++) {
            float w = __expf(d[u]);
            accv = fmaf(w, vv[u], accv);
            accw += w;
        }
    }
    for (; j < nc; j++) {
        int s = s_nbr[j];
        size_t base = (size_t)(b * NNODE + s) * DD + h * DHH + lane;
        float d = q * Km[base];
        float vvv = Vm[base];
        #pragma unroll
        for (int o = 16; o; o >>= 1) d += __shfl_xor_sync(0xffffffffu, d, o);
        float w = __expf(d);
        accv = fmaf(w, vvv, accv);
        accw += w;
    }
    Om[(size_t)bt * DD + h * DHH + lane] = accv / accw;
}

// ---------------- layernorm ----------------
template<int MODE>
__global__ void ln_k(const float* __restrict__ a, const float* __restrict__ bsrc,
                     const float* __restrict__ gam, const float* __restrict__ bet,
                     float* __restrict__ out)
{
    __shared__ float sm[8];
    size_t row = blockIdx.x;
    int i = threadIdx.x;
    float v = a[row * DD + i];
    float w = bsrc[row * DD + i];
    if (MODE == 1) w = fmaxf(w, 0.f);
    v += w;
    float mean = block_sum256(v, sm) * (1.f / DD);
    float d = v - mean;
    float var = block_sum256(d * d, sm) * (1.f / DD);
    out[row * DD + i] = d * rsqrtf(var + 1e-5f) * gam[i] + bet[i];
}

// ---------------- host-side GEMM dispatch ----------------
static void gemm(bool bt, int act, int M, int Nc, int K,
                 const float* A, int lda, const float* B, int ldb,
                 float* C, int ldc, const float* bias)
{
    dim3 g(Nc / 128, M / 128, 1);
    if (!bt) {
        if (act) mma_gemm_k<false,1><<<g,256>>>(M,Nc,K,A,lda,B,ldb,C,ldc,bias);
        else     mma_gemm_k<false,0><<<g,256>>>(M,Nc,K,A,lda,B,ldb,C,ldc,bias);
    } else {
        if (act) mma_gemm_k<true,1><<<g,256>>>(M,Nc,K,A,lda,B,ldb,C,ldc,bias);
        else     mma_gemm_k<true,0><<<g,256>>>(M,Nc,K,A,lda,B,ldb,C,ldc,bias);
    }
}

extern "C" void kernel_launch(void* const* d_in, const int* in_sizes, int n_in,
                              void* d_out, int out_size)
{
    const float* emb  = (const float*)d_in[0];
    const int*   mask = (const int*)  d_in[2];
    const float* gatW = (const float*)d_in[4];
    const float* attS = (const float*)d_in[5];
    const float* attD = (const float*)d_in[6];
    const float* gatB = (const float*)d_in[7];
    const float* glnS = (const float*)d_in[8];
    const float* glnB = (const float*)d_in[9];
    const float* Wq = (const float*)d_in[10], *bq = (const float*)d_in[11];
    const float* Wk = (const float*)d_in[12], *bk = (const float*)d_in[13];
    const float* Wv = (const float*)d_in[14], *bv = (const float*)d_in[15];
    const float* Wo = (const float*)d_in[16], *bo = (const float*)d_in[17];
    const float* W1 = (const float*)d_in[18], *b1 = (const float*)d_in[19];
    const float* W2 = (const float*)d_in[20], *b2 = (const float*)d_in[21];
    const float* l1s = (const float*)d_in[22], *l1b = (const float*)d_in[23];
    const float* l2s = (const float*)d_in[24], *l2b = (const float*)d_in[25];
    float* out = (float*)d_out;

    float *XC,*HB,*AS,*AD,*Q,*Kb,*V,*AO,*Y,*FF; unsigned* BITS; int *NBR,*CNT;
    cudaGetSymbolAddress((void**)&XC, g_XC);
    cudaGetSymbolAddress((void**)&HB, g_HB);
    cudaGetSymbolAddress((void**)&AS, g_AS);
    cudaGetSymbolAddress((void**)&AD, g_AD);
    cudaGetSymbolAddress((void**)&Q,  g_Q);
    cudaGetSymbolAddress((void**)&Kb, g_K);
    cudaGetSymbolAddress((void**)&V,  g_V);
    cudaGetSymbolAddress((void**)&AO, g_AO);
    cudaGetSymbolAddress((void**)&Y,  g_Y);
    cudaGetSymbolAddress((void**)&FF, g_FF);
    cudaGetSymbolAddress((void**)&BITS, g_BITS);
    cudaGetSymbolAddress((void**)&NBR, g_NBR);
    cudaGetSymbolAddress((void**)&CNT, g_CNT);

    const int M = BB * NNODE;                 // 8192

    pack_adj_k<<<(BB*32*NNODE)/256, 256>>>(mask, BITS);
    build_nbr_k<<<(BB*NNODE)/256, 256>>>(BITS, NBR, CNT);

    // ---- GAT stack ----
    const float* x = emb;
    for (int l = 0; l < LGN; l++) {
        gemm(true, 0, M, HH*DD, DD,
             x, DD, gatW + (size_t)l*HH*DD*DD, DD,
             HB, HH*DD, nullptr);
        asad_k<<<M, 256>>>(HB, attS + l*HH*DD, attD + l*HH*DD, AS, AD);
        gat_agg_k<<<M, 256>>>(HB, AS, AD, NBR, CNT, gatB + l*DD, Y);
        x = Y;
    }
    ln_k<1><<<M, 256>>>(emb, Y, glnS, glnB, XC);

    // ---- transformer layers ----
    for (int l = 0; l < LTN; l++) {
        gemm(false, 0, M, DD, DD, XC, DD, Wq + (size_t)l*DD*DD, DD, Q,  DD, bq + l*DD);
        gemm(false, 0, M, DD, DD, XC, DD, Wk + (size_t)l*DD*DD, DD, Kb, DD, bk + l*DD);
        gemm(false, 0, M, DD, DD, XC, DD, Wv + (size_t)l*DD*DD, DD, V,  DD, bv + l*DD);
        attn_sparse_k<<<M, 256>>>(Q, Kb, V, NBR, CNT, AO);
        gemm(false, 0, M, DD, DD, AO, DD, Wo + (size_t)l*DD*DD, DD, Y, DD, bo + l*DD);
        ln_k<0><<<M, 256>>>(XC, Y, l1s + l*DD, l1b + l*DD, XC);
        gemm(false, 1, M, DFFX, DD, XC, DD, W1 + (size_t)l*DD*DFFX, DFFX, FF, DFFX, b1 + l*DFFX);
        gemm(false, 0, M, DD, DFFX, FF, DFFX, W2 + (size_t)l*DFFX*DD, DD, Y, DD, b2 + l*DD);
        float* dst = (l == LTN - 1) ? out : XC;
        ln_k<0><<<M, 256>>>(XC, Y, l2s + l*DD, l2b + l*DD, dst);
    }
}

// round 4
// speedup vs baseline: 4.5258x; 1.6341x over previous
#include <cuda_runtime.h>
#include <cuda_fp16.h>
#include <math.h>

// ---------------- dims ----------------
#define BB    8
#define NNODE 1024
#define DD    256
#define HH    8
#define DHH   32
#define DFFX  1024
#define LGN   2
#define LTN   2
#define NBCAP 256
#define MTOT  (BB*NNODE)

// ---------------- scratch (device globals; no runtime allocation) ----------------
__device__ float    g_XC[MTOT*DD];
__device__ __half   g_HBH[MTOT*HH*DD];      // GAT per-head features (fp16)
__device__ float    g_AS[MTOT*HH];
__device__ float    g_AD[MTOT*HH];
__device__ float    g_ASP[32*MTOT];         // asad partials per 64-col tile
__device__ float    g_ADP[32*MTOT];
__device__ float    g_Q [MTOT*DD];
__device__ __half   g_KH[MTOT*DD];
__device__ __half   g_VH[MTOT*DD];
__device__ float    g_AO[MTOT*DD];
__device__ float    g_Y [MTOT*DD];
__device__ float    g_FF[MTOT*DFFX];
__device__ unsigned g_BITS[MTOT*(NNODE/32)];
__device__ int      g_NBR[MTOT*NBCAP];
__device__ int      g_CNT[MTOT];

// ---------------- helpers ----------------
__device__ __forceinline__ float block_sum256(float v, float* sm) {
    #pragma unroll
    for (int o = 16; o; o >>= 1) v += __shfl_xor_sync(0xffffffffu, v, o);
    int w = threadIdx.x >> 5;
    if ((threadIdx.x & 31) == 0) sm[w] = v;
    __syncthreads();
    if (threadIdx.x < 8) {
        v = sm[threadIdx.x];
        #pragma unroll
        for (int o = 4; o; o >>= 1) v += __shfl_xor_sync(0xffu, v, o);
        if (threadIdx.x == 0) sm[0] = v;
    }
    __syncthreads();
    v = sm[0];
    __syncthreads();
    return v;
}

__device__ __forceinline__ unsigned f2tf(float x) {
    unsigned r;
    asm("cvt.rna.tf32.f32 %0, %1;" : "=r"(r) : "f"(x));
    return r;
}

__device__ __forceinline__ void mma_tf32(float* c, const unsigned* a, const unsigned* b) {
    asm volatile(
        "mma.sync.aligned.m16n8k8.row.col.f32.tf32.tf32.f32 "
        "{%0,%1,%2,%3}, {%4,%5,%6,%7}, {%8,%9}, {%0,%1,%2,%3};\n"
        : "+f"(c[0]), "+f"(c[1]), "+f"(c[2]), "+f"(c[3])
        : "r"(a[0]), "r"(a[1]), "r"(a[2]), "r"(a[3]), "r"(b[0]), "r"(b[1]));
}

__device__ __forceinline__ unsigned saddr(const void* p) {
    return (unsigned)__cvta_generic_to_shared(p);
}
__device__ __forceinline__ void cp16(unsigned dst, const void* src) {
    asm volatile("cp.async.cg.shared.global [%0], [%1], 16;\n" :: "r"(dst), "l"(src));
}
__device__ __forceinline__ void cp_commit() {
    asm volatile("cp.async.commit_group;\n" ::: "memory");
}
template<int N>
__device__ __forceinline__ void cp_wait() {
    asm volatile("cp.async.wait_group %0;\n" :: "n"(N) : "memory");
}

// ---------------- adjacency pack ----------------
__global__ void pack_adj_k(const int* __restrict__ mask, unsigned* __restrict__ bits) {
    int idx = blockIdx.x * blockDim.x + threadIdx.x;
    int t  = idx & (NNODE - 1);
    int sw = (idx >> 10) & 31;
    int b  = idx >> 15;
    const int* mp = mask + ((size_t)b * NNODE + (size_t)sw * 32) * NNODE + t;
    unsigned w = 0;
    #pragma unroll
    for (int i = 0; i < 32; i++)
        if (mp[(size_t)i * NNODE] > 0) w |= (1u << i);
    int s0 = sw * 32;
    if (t >= s0 && t < s0 + 32) w |= (1u << (t - s0));
    bits[(b * NNODE + t) * 32 + sw] = w;
}

// ---------------- neighbor list build ----------------
__global__ void build_nbr_k(const unsigned* __restrict__ bits,
                            int* __restrict__ nbr, int* __restrict__ cnt) {
    int bt = blockIdx.x * blockDim.x + threadIdx.x;
    if (bt >= MTOT) return;
    const unsigned* bw = bits + (size_t)bt * 32;
    int* np = nbr + (size_t)bt * NBCAP;
    int c = 0;
    #pragma unroll 4
    for (int w = 0; w < 32; w++) {
        unsigned m = bw[w];
        while (m) {
            int bit = __ffs(m) - 1;
            m &= m - 1;
            if (c < NBCAP) np[c] = w * 32 + bit;
            c++;
        }
    }
    cnt[bt] = c < NBCAP ? c : NBCAP;
}

// ---------------- TF32 tensor-core GEMM, 2-stage cp.async pipeline ----------------
// C[M,N] = A[M,K] @ op(B) (+bias)(relu if ACT). op(B)=B^T if BT (B stored [N,K]).
// HALF_OUT: write __half. ASAD: also produce per-64col-tile partial dots with attS/attD.
// Requires: M%128==0, N%128==0, K%16==0.
template<bool BT, int ACT, int HALF_OUT, int ASAD>
__global__ void __launch_bounds__(256) mma_gemm_k(
    int M, int Ncol, int K,
    const float* __restrict__ A, int lda,
    const float* __restrict__ B, int ldb,
    void* __restrict__ Cv, int ldc,
    const float* __restrict__ bias,
    const float* __restrict__ attS, const float* __restrict__ attD,
    float* __restrict__ ASP, float* __restrict__ ADP)
{
    __shared__ float sA[2][128 * 20];
    __shared__ float sB[2][2560];     // BT: [128][20]; !BT: [16][136]
    const int tid  = threadIdx.x;
    const int lane = tid & 31, wid = tid >> 5;
    const int wm = wid & 3, wn = wid >> 2;
    const int m0 = blockIdx.y * 128, n0 = blockIdx.x * 128;
    const int r = lane >> 2, cq = lane & 3;

    float acc[2][8][4];
    #pragma unroll
    for (int mt = 0; mt < 2; mt++)
        #pragma unroll
        for (int nt = 0; nt < 8; nt++)
            #pragma unroll
            for (int u = 0; u < 4; u++) acc[mt][nt][u] = 0.f;

    const int T = K / 16;

    auto loadTiles = [&](int st, int k0) {
        #pragma unroll
        for (int i = 0; i < 2; i++) {
            int idx = tid * 2 + i;
            int m = idx >> 2, kq = idx & 3;
            cp16(saddr(&sA[st][m * 20 + kq * 4]),
                 A + (size_t)(m0 + m) * lda + k0 + kq * 4);
        }
        if (BT) {
            #pragma unroll
            for (int i = 0; i < 2; i++) {
                int idx = tid * 2 + i;
                int n = idx >> 2, kq = idx & 3;
                cp16(saddr(&sB[st][n * 20 + kq * 4]),
                     B + (size_t)(n0 + n) * ldb + k0 + kq * 4);
            }
        } else {
            #pragma unroll
            for (int i = 0; i < 2; i++) {
                int idx = tid * 2 + i;
                int kk = idx >> 5, nq = idx & 31;
                cp16(saddr(&sB[st][kk * 136 + nq * 4]),
                     B + (size_t)(k0 + kk) * ldb + n0 + nq * 4);
            }
        }
        cp_commit();
    };

    loadTiles(0, 0);
    for (int t = 0; t < T; t++) {
        if (t + 1 < T) { loadTiles((t + 1) & 1, (t + 1) * 16); cp_wait<1>(); }
        else           { cp_wait<0>(); }
        __syncthreads();
        const int st = t & 1;
        #pragma unroll
        for (int ks = 0; ks < 2; ks++) {
            const int kb = ks * 8;
            unsigned af[2][4], bf[8][2];
            #pragma unroll
            for (int mt = 0; mt < 2; mt++) {
                int mrow = wm * 32 + mt * 16;
                af[mt][0] = f2tf(sA[st][(mrow + r    ) * 20 + kb + cq    ]);
                af[mt][1] = f2tf(sA[st][(mrow + r + 8) * 20 + kb + cq    ]);
                af[mt][2] = f2tf(sA[st][(mrow + r    ) * 20 + kb + cq + 4]);
                af[mt][3] = f2tf(sA[st][(mrow + r + 8) * 20 + kb + cq + 4]);
            }
            #pragma unroll
            for (int nt = 0; nt < 8; nt++) {
                int nn = wn * 64 + nt * 8 + r;
                if (BT) {
                    bf[nt][0] = f2tf(sB[st][nn * 20 + kb + cq    ]);
                    bf[nt][1] = f2tf(sB[st][nn * 20 + kb + cq + 4]);
                } else {
                    bf[nt][0] = f2tf(sB[st][(kb + cq    ) * 136 + nn]);
                    bf[nt][1] = f2tf(sB[st][(kb + cq + 4) * 136 + nn]);
                }
            }
            #pragma unroll
            for (int mt = 0; mt < 2; mt++)
                #pragma unroll
                for (int nt = 0; nt < 8; nt++)
                    mma_tf32(acc[mt][nt], af[mt], bf[nt]);
        }
        __syncthreads();
    }

    // ---- optional asad partial dots (GAT projection only) ----
    if (ASAD) {
        float sS[2][2] = {{0,0},{0,0}}, sD[2][2] = {{0,0},{0,0}};
        #pragma unroll
        for (int mt = 0; mt < 2; mt++)
            #pragma unroll
            for (int nt = 0; nt < 8; nt++)
                #pragma unroll
                for (int u = 0; u < 4; u++) {
                    int g = n0 + wn * 64 + nt * 8 + cq * 2 + (u & 1);
                    float v = acc[mt][nt][u];
                    sS[mt][u >> 1] += v * attS[g];
                    sD[mt][u >> 1] += v * attD[g];
                }
        #pragma unroll
        for (int o = 1; o <= 2; o <<= 1)
            #pragma unroll
            for (int mt = 0; mt < 2; mt++)
                #pragma unroll
                for (int q = 0; q < 2; q++) {
                    sS[mt][q] += __shfl_xor_sync(0xffffffffu, sS[mt][q], o);
                    sD[mt][q] += __shfl_xor_sync(0xffffffffu, sD[mt][q], o);
                }
        if (cq == 0) {
            int j = (n0 >> 6) + wn;   // 0..31
            #pragma unroll
            for (int mt = 0; mt < 2; mt++)
                #pragma unroll
                for (int q = 0; q < 2; q++) {
                    int row = m0 + wm * 32 + mt * 16 + r + q * 8;
                    ASP[(size_t)j * M + row] = sS[mt][q];
                    ADP[(size_t)j * M + row] = sD[mt][q];
                }
        }
    }

    // ---- epilogue stores ----
    #pragma unroll
    for (int mt = 0; mt < 2; mt++) {
        int mrow = m0 + wm * 32 + mt * 16 + r;
        #pragma unroll
        for (int nt = 0; nt < 8; nt++) {
            int ncol = n0 + wn * 64 + nt * 8 + cq * 2;
            float* ac = acc[mt][nt];
            float2 v0 = make_float2(ac[0], ac[1]);
            float2 v1 = make_float2(ac[2], ac[3]);
            if (bias) {
                float b0 = bias[ncol], b1 = bias[ncol + 1];
                v0.x += b0; v0.y += b1; v1.x += b0; v1.y += b1;
            }
            if (ACT == 1) {
                v0.x = fmaxf(v0.x, 0.f); v0.y = fmaxf(v0.y, 0.f);
                v1.x = fmaxf(v1.x, 0.f); v1.y = fmaxf(v1.y, 0.f);
            }
            if (HALF_OUT) {
                __half* Ch = (__half*)Cv;
                *(__half2*)(Ch + (size_t)mrow * ldc + ncol) = __floats2half2_rn(v0.x, v0.y);
                *(__half2*)(Ch + (size_t)(mrow + 8) * ldc + ncol) = __floats2half2_rn(v1.x, v1.y);
            } else {
                float* Cf = (float*)Cv;
                *(float2*)(Cf + (size_t)mrow * ldc + ncol) = v0;
                *(float2*)(Cf + (size_t)(mrow + 8) * ldc + ncol) = v1;
            }
        }
    }
}

// ---------------- asad reduce: AS/AD[row][h] = sum of 4 col-tile partials ----------------
__global__ void asad_reduce_k(const float* __restrict__ ASP, const float* __restrict__ ADP,
                              float* __restrict__ as_, float* __restrict__ ad_)
{
    int idx = blockIdx.x * 256 + threadIdx.x;   // MTOT*8
    int row = idx >> 3, h = idx & 7;
    float s = 0.f, d = 0.f;
    #pragma unroll
    for (int j = 4 * h; j < 4 * h + 4; j++) {
        s += ASP[(size_t)j * MTOT + row];
        d += ADP[(size_t)j * MTOT + row];
    }
    as_[row * 8 + h] = s;
    ad_[row * 8 + h] = d;
}

// ---------------- sparse GAT aggregation (fp16 features) ----------------
__global__ void __launch_bounds__(256) gat_agg_k(
    const __half* __restrict__ hb, const float* __restrict__ as_,
    const float* __restrict__ ad_, const int* __restrict__ nbr,
    const int* __restrict__ cnt, const float* __restrict__ bias,
    float* __restrict__ y)
{
    __shared__ int   s_nbr[NBCAP];
    __shared__ float s_alpha[HH][NBCAP];
    __shared__ float s_inv[HH];
    __shared__ float4 s_red[4][64];
    int bt  = blockIdx.x;
    int b   = bt >> 10;
    int tid = threadIdx.x;
    int nc  = cnt[bt];
    for (int j = tid; j < nc; j += 256) s_nbr[j] = nbr[(size_t)bt * NBCAP + j];
    __syncthreads();

    for (int j = tid; j < nc; j += 256) {
        int s = s_nbr[j];
        const float* ap = as_ + (size_t)(b * NNODE + s) * HH;
        #pragma unroll
        for (int h = 0; h < HH; h++) {
            float e = ad_[bt * HH + h] + ap[h];
            e = e >= 0.f ? e : 0.2f * e;
            s_alpha[h][j] = __expf(e);
        }
    }
    __syncthreads();

    int wid = tid >> 5, lane = tid & 31;
    {
        float sum = 0.f;
        for (int j = lane; j < nc; j += 32) sum += s_alpha[wid][j];
        #pragma unroll
        for (int o = 16; o; o >>= 1) sum += __shfl_xor_sync(0xffffffffu, sum, o);
        if (lane == 0) s_inv[wid] = 1.f / (8.f * sum);
    }
    __syncthreads();
    for (int j = tid; j < nc; j += 256) {
        #pragma unroll
        for (int h = 0; h < HH; h++) s_alpha[h][j] *= s_inv[h];
    }
    __syncthreads();

    int hp = tid >> 6;
    int h0 = hp * 2;
    int cg = tid & 63;
    int c4 = cg * 4;
    float a0 = 0.f, a1 = 0.f, a2 = 0.f, a3 = 0.f;
    for (int j = 0; j < nc; j++) {
        int s = s_nbr[j];
        const __half* base = hb + (size_t)(b * NNODE + s) * (HH * DD);
        float w0 = s_alpha[h0][j], w1 = s_alpha[h0 + 1][j];
        const __half2* p0 = (const __half2*)(base + h0 * DD + c4);
        const __half2* p1 = (const __half2*)(base + (h0 + 1) * DD + c4);
        float2 u0 = __half22float2(p0[0]), u1 = __half22float2(p0[1]);
        float2 w0v = __half22float2(p1[0]), w1v = __half22float2(p1[1]);
        a0 = fmaf(w0, u0.x, fmaf(w1, w0v.x, a0));
        a1 = fmaf(w0, u0.y, fmaf(w1, w0v.y, a1));
        a2 = fmaf(w0, u1.x, fmaf(w1, w1v.x, a2));
        a3 = fmaf(w0, u1.y, fmaf(w1, w1v.y, a3));
    }
    s_red[hp][cg] = make_float4(a0, a1, a2, a3);
    __syncthreads();
    {
        int c = tid;
        const float* r0 = (const float*)&s_red[0][c >> 2];
        const float* r1 = (const float*)&s_red[1][c >> 2];
        const float* r2 = (const float*)&s_red[2][c >> 2];
        const float* r3 = (const float*)&s_red[3][c >> 2];
        int u = c & 3;
        y[(size_t)bt * DD + c] = r0[u] + r1[u] + r2[u] + r3[u] + bias[c];
    }
}

// ---------------- sparse masked attention (fp16 K/V) ----------------
__global__ void __launch_bounds__(256) attn_sparse_k(
    const float* __restrict__ Qm, const __half* __restrict__ Km,
    const __half* __restrict__ Vm, const int* __restrict__ nbr,
    const int* __restrict__ cnt, float* __restrict__ Om)
{
    __shared__ int s_nbr[NBCAP];
    int bt  = blockIdx.x;
    int b   = bt >> 10;
    int tid = threadIdx.x;
    int nc  = cnt[bt];
    for (int j = tid; j < nc; j += 256) s_nbr[j] = nbr[(size_t)bt * NBCAP + j];
    __syncthreads();
    int h = tid >> 5, lane = tid & 31;
    float q = Qm[(size_t)bt * DD + h * DHH + lane] * 0.17677669529663687f;
    float accv = 0.f, accw = 0.f;
    int j = 0;
    for (; j + 4 <= nc; j += 4) {
        float d[4], vv[4];
        #pragma unroll
        for (int u = 0; u < 4; u++) {
            int s = s_nbr[j + u];
            size_t base = (size_t)(b * NNODE + s) * DD + h * DHH + lane;
            d[u]  = q * __half2float(Km[base]);
            vv[u] = __half2float(Vm[base]);
        }
        #pragma unroll
        for (int o = 16; o; o >>= 1) {
            #pragma unroll
            for (int u = 0; u < 4; u++) d[u] += __shfl_xor_sync(0xffffffffu, d[u], o);
        }
        #pragma unroll
        for (int u = 0; u < 4; u++) {
            float w = __expf(d[u]);
            accv = fmaf(w, vv[u], accv);
            accw += w;
        }
    }
    for (; j < nc; j++) {
        int s = s_nbr[j];
        size_t base = (size_t)(b * NNODE + s) * DD + h * DHH + lane;
        float d = q * __half2float(Km[base]);
        float vvv = __half2float(Vm[base]);
        #pragma unroll
        for (int o = 16; o; o >>= 1) d += __shfl_xor_sync(0xffffffffu, d, o);
        float w = __expf(d);
        accv = fmaf(w, vvv, accv);
        accw += w;
    }
    Om[(size_t)bt * DD + h * DHH + lane] = accv / accw;
}

// ---------------- layernorm ----------------
template<int MODE>
__global__ void ln_k(const float* __restrict__ a, const float* __restrict__ bsrc,
                     const float* __restrict__ gam, const float* __restrict__ bet,
                     float* __restrict__ out)
{
    __shared__ float sm[8];
    size_t row = blockIdx.x;
    int i = threadIdx.x;
    float v = a[row * DD + i];
    float w = bsrc[row * DD + i];
    if (MODE == 1) w = fmaxf(w, 0.f);
    v += w;
    float mean = block_sum256(v, sm) * (1.f / DD);
    float d = v - mean;
    float var = block_sum256(d * d, sm) * (1.f / DD);
    out[row * DD + i] = d * rsqrtf(var + 1e-5f) * gam[i] + bet[i];
}

extern "C" void kernel_launch(void* const* d_in, const int* in_sizes, int n_in,
                              void* d_out, int out_size)
{
    const float* emb  = (const float*)d_in[0];
    const int*   mask = (const int*)  d_in[2];
    const float* gatW = (const float*)d_in[4];
    const float* attS = (const float*)d_in[5];
    const float* attD = (const float*)d_in[6];
    const float* gatB = (const float*)d_in[7];
    const float* glnS = (const float*)d_in[8];
    const float* glnB = (const float*)d_in[9];
    const float* Wq = (const float*)d_in[10], *bq = (const float*)d_in[11];
    const float* Wk = (const float*)d_in[12], *bk = (const float*)d_in[13];
    const float* Wv = (const float*)d_in[14], *bv = (const float*)d_in[15];
    const float* Wo = (const float*)d_in[16], *bo = (const float*)d_in[17];
    const float* W1 = (const float*)d_in[18], *b1 = (const float*)d_in[19];
    const float* W2 = (const float*)d_in[20], *b2 = (const float*)d_in[21];
    const float* l1s = (const float*)d_in[22], *l1b = (const float*)d_in[23];
    const float* l2s = (const float*)d_in[24], *l2b = (const float*)d_in[25];
    float* out = (float*)d_out;

    float *XC,*AS,*AD,*ASP,*ADP,*Q,*AO,*Y,*FF; __half *HBH,*KH,*VH;
    unsigned* BITS; int *NBR,*CNT;
    cudaGetSymbolAddress((void**)&XC, g_XC);
    cudaGetSymbolAddress((void**)&HBH, g_HBH);
    cudaGetSymbolAddress((void**)&AS, g_AS);
    cudaGetSymbolAddress((void**)&AD, g_AD);
    cudaGetSymbolAddress((void**)&ASP, g_ASP);
    cudaGetSymbolAddress((void**)&ADP, g_ADP);
    cudaGetSymbolAddress((void**)&Q,  g_Q);
    cudaGetSymbolAddress((void**)&KH, g_KH);
    cudaGetSymbolAddress((void**)&VH, g_VH);
    cudaGetSymbolAddress((void**)&AO, g_AO);
    cudaGetSymbolAddress((void**)&Y,  g_Y);
    cudaGetSymbolAddress((void**)&FF, g_FF);
    cudaGetSymbolAddress((void**)&BITS, g_BITS);
    cudaGetSymbolAddress((void**)&NBR, g_NBR);
    cudaGetSymbolAddress((void**)&CNT, g_CNT);

    const int M = MTOT;

    pack_adj_k<<<(BB*32*NNODE)/256, 256>>>(mask, BITS);
    build_nbr_k<<<(MTOT)/256, 256>>>(BITS, NBR, CNT);

    // ---- GAT stack ----
    const float* x = emb;
    for (int l = 0; l < LGN; l++) {
        // h = x @ gatW[l]^T -> fp16 HBH, plus asad partials in epilogue
        mma_gemm_k<true,0,1,1><<<dim3((HH*DD)/128, M/128), 256>>>(
            M, HH*DD, DD, x, DD, gatW + (size_t)l*HH*DD*DD, DD,
            HBH, HH*DD, nullptr, attS + l*HH*DD, attD + l*HH*DD, ASP, ADP);
        asad_reduce_k<<<(MTOT*8)/256, 256>>>(ASP, ADP, AS, AD);
        gat_agg_k<<<M, 256>>>(HBH, AS, AD, NBR, CNT, gatB + l*DD, Y);
        x = Y;
    }
    ln_k<1><<<M, 256>>>(emb, Y, glnS, glnB, XC);

    // ---- transformer layers ----
    for (int l = 0; l < LTN; l++) {
        mma_gemm_k<false,0,0,0><<<dim3(DD/128, M/128), 256>>>(
            M, DD, DD, XC, DD, Wq + (size_t)l*DD*DD, DD, Q, DD,
            bq + l*DD, nullptr, nullptr, nullptr, nullptr);
        mma_gemm_k<false,0,1,0><<<dim3(DD/128, M/128), 256>>>(
            M, DD, DD, XC, DD, Wk + (size_t)l*DD*DD, DD, KH, DD,
            bk + l*DD, nullptr, nullptr, nullptr, nullptr);
        mma_gemm_k<false,0,1,0><<<dim3(DD/128, M/128), 256>>>(
            M, DD, DD, XC, DD, Wv + (size_t)l*DD*DD, DD, VH, DD,
            bv + l*DD, nullptr, nullptr, nullptr, nullptr);
        attn_sparse_k<<<M, 256>>>(Q, KH, VH, NBR, CNT, AO);
        mma_gemm_k<false,0,0,0><<<dim3(DD/128, M/128), 256>>>(
            M, DD, DD, AO, DD, Wo + (size_t)l*DD*DD, DD, Y, DD,
            bo + l*DD, nullptr, nullptr, nullptr, nullptr);
        ln_k<0><<<M, 256>>>(XC, Y, l1s + l*DD, l1b + l*DD, XC);
        mma_gemm_k<false,1,0,0><<<dim3(DFFX/128, M/128), 256>>>(
            M, DFFX, DD, XC, DD, W1 + (size_t)l*DD*DFFX, DFFX, FF, DFFX,
            b1 + l*DFFX, nullptr, nullptr, nullptr, nullptr);
        mma_gemm_k<false,0,0,0><<<dim3(DD/128, M/128), 256>>>(
            M, DD, DFFX, FF, DFFX, W2 + (size_t)l*DFFX*DD, DD, Y, DD,
            b2 + l*DD, nullptr, nullptr, nullptr, nullptr);
        float* dst = (l == LTN - 1) ? out : XC;
        ln_k<0><<<M, 256>>>(XC, Y, l2s + l*DD, l2b + l*DD, dst);
    }
}

// round 5
// speedup vs baseline: 4.5546x; 1.0064x over previous
#include <cuda_runtime.h>
#include <cuda_fp16.h>
#include <math.h>

// ---------------- dims ----------------
#define BB    8
#define NNODE 1024
#define DD    256
#define HH    8
#define DHH   32
#define DFFX  1024
#define LGN   2
#define LTN   2
#define NBCAP 256
#define MTOT  (BB*NNODE)

// ---------------- scratch (device globals; no runtime allocation) ----------------
__device__ float    g_XC[MTOT*DD];
__device__ __half   g_HBH[MTOT*HH*DD];      // GAT per-head features (fp16)
__device__ float    g_AS[MTOT*HH];
__device__ float    g_AD[MTOT*HH];
__device__ float    g_ASP[32*MTOT];         // asad partials per 64-col tile
__device__ float    g_ADP[32*MTOT];
__device__ __half   g_QKVH[MTOT*3*DD];      // fused QKV (fp16)
__device__ float    g_WQKV[LTN*DD*3*DD];    // packed QKV weights
__device__ float    g_BQKV[LTN*3*DD];
__device__ float    g_AO[MTOT*DD];
__device__ float    g_Y [MTOT*DD];
__device__ float    g_FF[MTOT*DFFX];
__device__ unsigned g_BITS[MTOT*(NNODE/32)];
__device__ int      g_NBR[MTOT*NBCAP];
__device__ int      g_CNT[MTOT];

// ---------------- helpers ----------------
__device__ __forceinline__ float block_sum256(float v, float* sm) {
    #pragma unroll
    for (int o = 16; o; o >>= 1) v += __shfl_xor_sync(0xffffffffu, v, o);
    int w = threadIdx.x >> 5;
    if ((threadIdx.x & 31) == 0) sm[w] = v;
    __syncthreads();
    if (threadIdx.x < 8) {
        v = sm[threadIdx.x];
        #pragma unroll
        for (int o = 4; o; o >>= 1) v += __shfl_xor_sync(0xffu, v, o);
        if (threadIdx.x == 0) sm[0] = v;
    }
    __syncthreads();
    v = sm[0];
    __syncthreads();
    return v;
}

__device__ __forceinline__ unsigned packh2(float x, float y) {
    __half2 h = __floats2half2_rn(x, y);
    return *(unsigned*)&h;
}
__device__ __forceinline__ unsigned packh2v(float2 v) { return packh2(v.x, v.y); }

__device__ __forceinline__ void mma_f16(float* c, const unsigned* a, const unsigned* b) {
    asm volatile(
        "mma.sync.aligned.m16n8k16.row.col.f32.f16.f16.f32 "
        "{%0,%1,%2,%3}, {%4,%5,%6,%7}, {%8,%9}, {%0,%1,%2,%3};\n"
        : "+f"(c[0]), "+f"(c[1]), "+f"(c[2]), "+f"(c[3])
        : "r"(a[0]), "r"(a[1]), "r"(a[2]), "r"(a[3]), "r"(b[0]), "r"(b[1]));
}

__device__ __forceinline__ unsigned saddr(const void* p) {
    return (unsigned)__cvta_generic_to_shared(p);
}
__device__ __forceinline__ void cp16(unsigned dst, const void* src) {
    asm volatile("cp.async.cg.shared.global [%0], [%1], 16;\n" :: "r"(dst), "l"(src));
}
__device__ __forceinline__ void cp_commit() {
    asm volatile("cp.async.commit_group;\n" ::: "memory");
}
template<int N>
__device__ __forceinline__ void cp_wait() {
    asm volatile("cp.async.wait_group %0;\n" :: "n"(N) : "memory");
}

// ---------------- adjacency pack ----------------
__global__ void pack_adj_k(const int* __restrict__ mask, unsigned* __restrict__ bits) {
    int idx = blockIdx.x * blockDim.x + threadIdx.x;
    int t  = idx & (NNODE - 1);
    int sw = (idx >> 10) & 31;
    int b  = idx >> 15;
    const int* mp = mask + ((size_t)b * NNODE + (size_t)sw * 32) * NNODE + t;
    unsigned w = 0;
    #pragma unroll
    for (int i = 0; i < 32; i++)
        if (mp[(size_t)i * NNODE] > 0) w |= (1u << i);
    int s0 = sw * 32;
    if (t >= s0 && t < s0 + 32) w |= (1u << (t - s0));
    bits[(b * NNODE + t) * 32 + sw] = w;
}

// ---------------- neighbor list build ----------------
__global__ void build_nbr_k(const unsigned* __restrict__ bits,
                            int* __restrict__ nbr, int* __restrict__ cnt) {
    int bt = blockIdx.x * blockDim.x + threadIdx.x;
    if (bt >= MTOT) return;
    const unsigned* bw = bits + (size_t)bt * 32;
    int* np = nbr + (size_t)bt * NBCAP;
    int c = 0;
    #pragma unroll 4
    for (int w = 0; w < 32; w++) {
        unsigned m = bw[w];
        while (m) {
            int bit = __ffs(m) - 1;
            m &= m - 1;
            if (c < NBCAP) np[c] = w * 32 + bit;
            c++;
        }
    }
    cnt[bt] = c < NBCAP ? c : NBCAP;
}

// ---------------- QKV weight/bias pack ----------------
__global__ void pack_qkv_k(const float* __restrict__ Wq, const float* __restrict__ Wk,
                           const float* __restrict__ Wv, const float* __restrict__ bq,
                           const float* __restrict__ bk, const float* __restrict__ bv,
                           float* __restrict__ W, float* __restrict__ Bb)
{
    int idx = blockIdx.x * 256 + threadIdx.x;   // LTN*DD*768
    if (idx >= LTN * DD * 3 * DD) return;
    int n = idx % (3 * DD);
    int k = (idx / (3 * DD)) % DD;
    int l = idx / (3 * DD * DD);
    float v;
    if (n < DD)            v = Wq[((size_t)l * DD + k) * DD + n];
    else if (n < 2 * DD)   v = Wk[((size_t)l * DD + k) * DD + n - DD];
    else                   v = Wv[((size_t)l * DD + k) * DD + n - 2 * DD];
    W[idx] = v;
    if (k == 0) {
        float bvv;
        if (n < DD)          bvv = bq[l * DD + n];
        else if (n < 2 * DD) bvv = bk[l * DD + n - DD];
        else                 bvv = bv[l * DD + n - 2 * DD];
        Bb[l * 3 * DD + n] = bvv;
    }
}

// ---------------- fp16 tensor-core GEMM, 2-stage cp.async pipeline ----------------
// C[M,N] = A[M,K] @ op(B) (+bias)(relu if ACT). op(B)=B^T if BT (B stored [N,K]).
// fp32 inputs converted to fp16 at fragment-load time; fp32 accumulate.
// HALF_OUT: write __half. ASAD: per-64col-tile partial dots with attS/attD.
template<bool BT, int ACT, int HALF_OUT, int ASAD>
__global__ void __launch_bounds__(256) mma_gemm_k(
    int M, int Ncol, int K,
    const float* __restrict__ A, int lda,
    const float* __restrict__ B, int ldb,
    void* __restrict__ Cv, int ldc,
    const float* __restrict__ bias,
    const float* __restrict__ attS, const float* __restrict__ attD,
    float* __restrict__ ASP, float* __restrict__ ADP)
{
    __shared__ float sA[2][128 * 20];
    __shared__ float sB[2][2560];     // BT: [128][20]; !BT: [16][136]
    const int tid  = threadIdx.x;
    const int lane = tid & 31, wid = tid >> 5;
    const int wm = wid & 3, wn = wid >> 2;
    const int m0 = blockIdx.y * 128, n0 = blockIdx.x * 128;
    const int r = lane >> 2, cq = lane & 3;

    float acc[2][8][4];
    #pragma unroll
    for (int mt = 0; mt < 2; mt++)
        #pragma unroll
        for (int nt = 0; nt < 8; nt++)
            #pragma unroll
            for (int u = 0; u < 4; u++) acc[mt][nt][u] = 0.f;

    const int T = K / 16;

    auto loadTiles = [&](int st, int k0) {
        #pragma unroll
        for (int i = 0; i < 2; i++) {
            int idx = tid * 2 + i;
            int m = idx >> 2, kq = idx & 3;
            cp16(saddr(&sA[st][m * 20 + kq * 4]),
                 A + (size_t)(m0 + m) * lda + k0 + kq * 4);
        }
        if (BT) {
            #pragma unroll
            for (int i = 0; i < 2; i++) {
                int idx = tid * 2 + i;
                int n = idx >> 2, kq = idx & 3;
                cp16(saddr(&sB[st][n * 20 + kq * 4]),
                     B + (size_t)(n0 + n) * ldb + k0 + kq * 4);
            }
        } else {
            #pragma unroll
            for (int i = 0; i < 2; i++) {
                int idx = tid * 2 + i;
                int kk = idx >> 5, nq = idx & 31;
                cp16(saddr(&sB[st][kk * 136 + nq * 4]),
                     B + (size_t)(k0 + kk) * ldb + n0 + nq * 4);
            }
        }
        cp_commit();
    };

    loadTiles(0, 0);
    for (int t = 0; t < T; t++) {
        if (t + 1 < T) { loadTiles((t + 1) & 1, (t + 1) * 16); cp_wait<1>(); }
        else           { cp_wait<0>(); }
        __syncthreads();
        const int st = t & 1;

        unsigned af[2][4], bf[8][2];
        #pragma unroll
        for (int mt = 0; mt < 2; mt++) {
            int mrow = wm * 32 + mt * 16;
            const float2* row0 = (const float2*)&sA[st][(mrow + r    ) * 20];
            const float2* row1 = (const float2*)&sA[st][(mrow + r + 8) * 20];
            af[mt][0] = packh2v(row0[cq]);
            af[mt][1] = packh2v(row1[cq]);
            af[mt][2] = packh2v(row0[cq + 4]);
            af[mt][3] = packh2v(row1[cq + 4]);
        }
        #pragma unroll
        for (int nt = 0; nt < 8; nt++) {
            int nn = wn * 64 + nt * 8 + r;
            if (BT) {
                const float2* rown = (const float2*)&sB[st][nn * 20];
                bf[nt][0] = packh2v(rown[cq]);
                bf[nt][1] = packh2v(rown[cq + 4]);
            } else {
                bf[nt][0] = packh2(sB[st][(2 * cq    ) * 136 + nn],
                                   sB[st][(2 * cq + 1) * 136 + nn]);
                bf[nt][1] = packh2(sB[st][(2 * cq + 8) * 136 + nn],
                                   sB[st][(2 * cq + 9) * 136 + nn]);
            }
        }
        #pragma unroll
        for (int mt = 0; mt < 2; mt++)
            #pragma unroll
            for (int nt = 0; nt < 8; nt++)
                mma_f16(acc[mt][nt], af[mt], bf[nt]);
        __syncthreads();
    }

    // ---- optional asad partial dots (GAT projection only) ----
    if (ASAD) {
        float sS[2][2] = {{0,0},{0,0}}, sD[2][2] = {{0,0},{0,0}};
        #pragma unroll
        for (int mt = 0; mt < 2; mt++)
            #pragma unroll
            for (int nt = 0; nt < 8; nt++)
                #pragma unroll
                for (int u = 0; u < 4; u++) {
                    int g = n0 + wn * 64 + nt * 8 + cq * 2 + (u & 1);
                    float v = acc[mt][nt][u];
                    sS[mt][u >> 1] += v * attS[g];
                    sD[mt][u >> 1] += v * attD[g];
                }
        #pragma unroll
        for (int o = 1; o <= 2; o <<= 1)
            #pragma unroll
            for (int mt = 0; mt < 2; mt++)
                #pragma unroll
                for (int q = 0; q < 2; q++) {
                    sS[mt][q] += __shfl_xor_sync(0xffffffffu, sS[mt][q], o);
                    sD[mt][q] += __shfl_xor_sync(0xffffffffu, sD[mt][q], o);
                }
        if (cq == 0) {
            int j = (n0 >> 6) + wn;
            #pragma unroll
            for (int mt = 0; mt < 2; mt++)
                #pragma unroll
                for (int q = 0; q < 2; q++) {
                    int row = m0 + wm * 32 + mt * 16 + r + q * 8;
                    ASP[(size_t)j * M + row] = sS[mt][q];
                    ADP[(size_t)j * M + row] = sD[mt][q];
                }
        }
    }

    // ---- epilogue stores ----
    #pragma unroll
    for (int mt = 0; mt < 2; mt++) {
        int mrow = m0 + wm * 32 + mt * 16 + r;
        #pragma unroll
        for (int nt = 0; nt < 8; nt++) {
            int ncol = n0 + wn * 64 + nt * 8 + cq * 2;
            float* ac = acc[mt][nt];
            float2 v0 = make_float2(ac[0], ac[1]);
            float2 v1 = make_float2(ac[2], ac[3]);
            if (bias) {
                float b0 = bias[ncol], b1 = bias[ncol + 1];
                v0.x += b0; v0.y += b1; v1.x += b0; v1.y += b1;
            }
            if (ACT == 1) {
                v0.x = fmaxf(v0.x, 0.f); v0.y = fmaxf(v0.y, 0.f);
                v1.x = fmaxf(v1.x, 0.f); v1.y = fmaxf(v1.y, 0.f);
            }
            if (HALF_OUT) {
                __half* Ch = (__half*)Cv;
                *(__half2*)(Ch + (size_t)mrow * ldc + ncol) = __floats2half2_rn(v0.x, v0.y);
                *(__half2*)(Ch + (size_t)(mrow + 8) * ldc + ncol) = __floats2half2_rn(v1.x, v1.y);
            } else {
                float* Cf = (float*)Cv;
                *(float2*)(Cf + (size_t)mrow * ldc + ncol) = v0;
                *(float2*)(Cf + (size_t)(mrow + 8) * ldc + ncol) = v1;
            }
        }
    }
}

// ---------------- asad reduce ----------------
__global__ void asad_reduce_k(const float* __restrict__ ASP, const float* __restrict__ ADP,
                              float* __restrict__ as_, float* __restrict__ ad_)
{
    int idx = blockIdx.x * 256 + threadIdx.x;   // MTOT*8
    int row = idx >> 3, h = idx & 7;
    float s = 0.f, d = 0.f;
    #pragma unroll
    for (int j = 4 * h; j < 4 * h + 4; j++) {
        s += ASP[(size_t)j * MTOT + row];
        d += ADP[(size_t)j * MTOT + row];
    }
    as_[row * 8 + h] = s;
    ad_[row * 8 + h] = d;
}

// ---------------- sparse GAT aggregation (fp16 features) ----------------
__global__ void __launch_bounds__(256) gat_agg_k(
    const __half* __restrict__ hb, const float* __restrict__ as_,
    const float* __restrict__ ad_, const int* __restrict__ nbr,
    const int* __restrict__ cnt, const float* __restrict__ bias,
    float* __restrict__ y)
{
    __shared__ int   s_nbr[NBCAP];
    __shared__ float s_alpha[HH][NBCAP];
    __shared__ float s_inv[HH];
    __shared__ float4 s_red[4][64];
    int bt  = blockIdx.x;
    int b   = bt >> 10;
    int tid = threadIdx.x;
    int nc  = cnt[bt];
    for (int j = tid; j < nc; j += 256) s_nbr[j] = nbr[(size_t)bt * NBCAP + j];
    __syncthreads();

    for (int j = tid; j < nc; j += 256) {
        int s = s_nbr[j];
        const float* ap = as_ + (size_t)(b * NNODE + s) * HH;
        #pragma unroll
        for (int h = 0; h < HH; h++) {
            float e = ad_[bt * HH + h] + ap[h];
            e = e >= 0.f ? e : 0.2f * e;
            s_alpha[h][j] = __expf(e);
        }
    }
    __syncthreads();

    int wid = tid >> 5, lane = tid & 31;
    {
        float sum = 0.f;
        for (int j = lane; j < nc; j += 32) sum += s_alpha[wid][j];
        #pragma unroll
        for (int o = 16; o; o >>= 1) sum += __shfl_xor_sync(0xffffffffu, sum, o);
        if (lane == 0) s_inv[wid] = 1.f / (8.f * sum);
    }
    __syncthreads();
    for (int j = tid; j < nc; j += 256) {
        #pragma unroll
        for (int h = 0; h < HH; h++) s_alpha[h][j] *= s_inv[h];
    }
    __syncthreads();

    int hp = tid >> 6;
    int h0 = hp * 2;
    int cg = tid & 63;
    int c4 = cg * 4;
    float a0 = 0.f, a1 = 0.f, a2 = 0.f, a3 = 0.f;
    for (int j = 0; j < nc; j++) {
        int s = s_nbr[j];
        const __half* base = hb + (size_t)(b * NNODE + s) * (HH * DD);
        float w0 = s_alpha[h0][j], w1 = s_alpha[h0 + 1][j];
        const __half2* p0 = (const __half2*)(base + h0 * DD + c4);
        const __half2* p1 = (const __half2*)(base + (h0 + 1) * DD + c4);
        float2 u0 = __half22float2(p0[0]), u1 = __half22float2(p0[1]);
        float2 w0v = __half22float2(p1[0]), w1v = __half22float2(p1[1]);
        a0 = fmaf(w0, u0.x, fmaf(w1, w0v.x, a0));
        a1 = fmaf(w0, u0.y, fmaf(w1, w0v.y, a1));
        a2 = fmaf(w0, u1.x, fmaf(w1, w1v.x, a2));
        a3 = fmaf(w0, u1.y, fmaf(w1, w1v.y, a3));
    }
    s_red[hp][cg] = make_float4(a0, a1, a2, a3);
    __syncthreads();
    {
        int c = tid;
        const float* r0 = (const float*)&s_red[0][c >> 2];
        const float* r1 = (const float*)&s_red[1][c >> 2];
        const float* r2 = (const float*)&s_red[2][c >> 2];
        const float* r3 = (const float*)&s_red[3][c >> 2];
        int u = c & 3;
        y[(size_t)bt * DD + c] = r0[u] + r1[u] + r2[u] + r3[u] + bias[c];
    }
}

// ---------------- sparse masked attention (fused fp16 QKV) ----------------
__global__ void __launch_bounds__(256) attn_sparse_k(
    const __half* __restrict__ QKV, const int* __restrict__ nbr,
    const int* __restrict__ cnt, float* __restrict__ Om)
{
    __shared__ int s_nbr[NBCAP];
    int bt  = blockIdx.x;
    int b   = bt >> 10;
    int tid = threadIdx.x;
    int nc  = cnt[bt];
    for (int j = tid; j < nc; j += 256) s_nbr[j] = nbr[(size_t)bt * NBCAP + j];
    __syncthreads();
    int h = tid >> 5, lane = tid & 31;
    const int LD3 = 3 * DD;
    float q = __half2float(QKV[(size_t)bt * LD3 + h * DHH + lane]) * 0.17677669529663687f;
    float accv = 0.f, accw = 0.f;
    int j = 0;
    for (; j + 4 <= nc; j += 4) {
        float d[4], vv[4];
        #pragma unroll
        for (int u = 0; u < 4; u++) {
            int s = s_nbr[j + u];
            size_t base = (size_t)(b * NNODE + s) * LD3 + h * DHH + lane;
            d[u]  = q * __half2float(QKV[base + DD]);
            vv[u] = __half2float(QKV[base + 2 * DD]);
        }
        #pragma unroll
        for (int o = 16; o; o >>= 1) {
            #pragma unroll
            for (int u = 0; u < 4; u++) d[u] += __shfl_xor_sync(0xffffffffu, d[u], o);
        }
        #pragma unroll
        for (int u = 0; u < 4; u++) {
            float w = __expf(d[u]);
            accv = fmaf(w, vv[u], accv);
            accw += w;
        }
    }
    for (; j < nc; j++) {
        int s = s_nbr[j];
        size_t base = (size_t)(b * NNODE + s) * LD3 + h * DHH + lane;
        float d = q * __half2float(QKV[base + DD]);
        float vvv = __half2float(QKV[base + 2 * DD]);
        #pragma unroll
        for (int o = 16; o; o >>= 1) d += __shfl_xor_sync(0xffffffffu, d, o);
        float w = __expf(d);
        accv = fmaf(w, vvv, accv);
        accw += w;
    }
    Om[(size_t)bt * DD + h * DHH + lane] = accv / accw;
}

// ---------------- layernorm ----------------
template<int MODE>
__global__ void ln_k(const float* __restrict__ a, const float* __restrict__ bsrc,
                     const float* __restrict__ gam, const float* __restrict__ bet,
                     float* __restrict__ out)
{
    __shared__ float sm[8];
    size_t row = blockIdx.x;
    int i = threadIdx.x;
    float v = a[row * DD + i];
    float w = bsrc[row * DD + i];
    if (MODE == 1) w = fmaxf(w, 0.f);
    v += w;
    float mean = block_sum256(v, sm) * (1.f / DD);
    float d = v - mean;
    float var = block_sum256(d * d, sm) * (1.f / DD);
    out[row * DD + i] = d * rsqrtf(var + 1e-5f) * gam[i] + bet[i];
}

extern "C" void kernel_launch(void* const* d_in, const int* in_sizes, int n_in,
                              void* d_out, int out_size)
{
    const float* emb  = (const float*)d_in[0];
    const int*   mask = (const int*)  d_in[2];
    const float* gatW = (const float*)d_in[4];
    const float* attS = (const float*)d_in[5];
    const float* attD = (const float*)d_in[6];
    const float* gatB = (const float*)d_in[7];
    const float* glnS = (const float*)d_in[8];
    const float* glnB = (const float*)d_in[9];
    const float* Wq = (const float*)d_in[10], *bq = (const float*)d_in[11];
    const float* Wk = (const float*)d_in[12], *bk = (const float*)d_in[13];
    const float* Wv = (const float*)d_in[14], *bv = (const float*)d_in[15];
    const float* Wo = (const float*)d_in[16], *bo = (const float*)d_in[17];
    const float* W1 = (const float*)d_in[18], *b1 = (const float*)d_in[19];
    const float* W2 = (const float*)d_in[20], *b2 = (const float*)d_in[21];
    const float* l1s = (const float*)d_in[22], *l1b = (const float*)d_in[23];
    const float* l2s = (const float*)d_in[24], *l2b = (const float*)d_in[25];
    float* out = (float*)d_out;

    float *XC,*AS,*AD,*ASP,*ADP,*WQKV,*BQKV,*AO,*Y,*FF;
    __half *HBH,*QKVH;
    unsigned* BITS; int *NBR,*CNT;
    cudaGetSymbolAddress((void**)&XC, g_XC);
    cudaGetSymbolAddress((void**)&HBH, g_HBH);
    cudaGetSymbolAddress((void**)&AS, g_AS);
    cudaGetSymbolAddress((void**)&AD, g_AD);
    cudaGetSymbolAddress((void**)&ASP, g_ASP);
    cudaGetSymbolAddress((void**)&ADP, g_ADP);
    cudaGetSymbolAddress((void**)&QKVH, g_QKVH);
    cudaGetSymbolAddress((void**)&WQKV, g_WQKV);
    cudaGetSymbolAddress((void**)&BQKV, g_BQKV);
    cudaGetSymbolAddress((void**)&AO, g_AO);
    cudaGetSymbolAddress((void**)&Y,  g_Y);
    cudaGetSymbolAddress((void**)&FF, g_FF);
    cudaGetSymbolAddress((void**)&BITS, g_BITS);
    cudaGetSymbolAddress((void**)&NBR, g_NBR);
    cudaGetSymbolAddress((void**)&CNT, g_CNT);

    const int M = MTOT;

    pack_adj_k<<<(BB*32*NNODE)/256, 256>>>(mask, BITS);
    build_nbr_k<<<(MTOT)/256, 256>>>(BITS, NBR, CNT);
    pack_qkv_k<<<(LTN*DD*3*DD + 255)/256, 256>>>(Wq, Wk, Wv, bq, bk, bv, WQKV, BQKV);

    // ---- GAT stack ----
    const float* x = emb;
    for (int l = 0; l < LGN; l++) {
        mma_gemm_k<true,0,1,1><<<dim3((HH*DD)/128, M/128), 256>>>(
            M, HH*DD, DD, x, DD, gatW + (size_t)l*HH*DD*DD, DD,
            HBH, HH*DD, nullptr, attS + l*HH*DD, attD + l*HH*DD, ASP, ADP);
        asad_reduce_k<<<(MTOT*8)/256, 256>>>(ASP, ADP, AS, AD);
        gat_agg_k<<<M, 256>>>(HBH, AS, AD, NBR, CNT, gatB + l*DD, Y);
        x = Y;
    }
    ln_k<1><<<M, 256>>>(emb, Y, glnS, glnB, XC);

    // ---- transformer layers ----
    for (int l = 0; l < LTN; l++) {
        mma_gemm_k<false,0,1,0><<<dim3((3*DD)/128, M/128), 256>>>(
            M, 3*DD, DD, XC, DD, WQKV + (size_t)l*DD*3*DD, 3*DD, QKVH, 3*DD,
            BQKV + l*3*DD, nullptr, nullptr, nullptr, nullptr);
        attn_sparse_k<<<M, 256>>>(QKVH, NBR, CNT, AO);
        mma_gemm_k<false,0,0,0><<<dim3(DD/128, M/128), 256>>>(
            M, DD, DD, AO, DD, Wo + (size_t)l*DD*DD, DD, Y, DD,
            bo + l*DD, nullptr, nullptr, nullptr, nullptr);
        ln_k<0><<<M, 256>>>(XC, Y, l1s + l*DD, l1b + l*DD, XC);
        mma_gemm_k<false,1,0,0><<<dim3(DFFX/128, M/128), 256>>>(
            M, DFFX, DD, XC, DD, W1 + (size_t)l*DD*DFFX, DFFX, FF, DFFX,
            b1 + l*DFFX, nullptr, nullptr, nullptr, nullptr);
        mma_gemm_k<false,0,0,0><<<dim3(DD/128, M/128), 256>>>(
            M, DD, DFFX, FF, DFFX, W2 + (size_t)l*DFFX*DD, DD, Y, DD,
            b2 + l*DD, nullptr, nullptr, nullptr, nullptr);
        float* dst = (l == LTN - 1) ? out : XC;
        ln_k<0><<<M, 256>>>(XC, Y, l2s + l*DD, l2b + l*DD, dst);
    }
}

// round 6
// speedup vs baseline: 5.6733x; 1.2456x over previous
#include <cuda_runtime.h>
#include <cuda_fp16.h>
#include <math.h>

// ---------------- dims ----------------
#define BB    8
#define NNODE 1024
#define DD    256
#define HH    8
#define DHH   32
#define DFFX  1024
#define LGN   2
#define LTN   2
#define NBCAP 256
#define MTOT  (BB*NNODE)

// ---------------- scratch (device globals; no runtime allocation) ----------------
__device__ float                 g_XC[MTOT*DD];
__device__ __align__(16) __half  g_XCH[MTOT*DD];
__device__ __align__(16) __half  g_EMBH[MTOT*DD];
__device__ __align__(16) __half  g_HBH[MTOT*HH*DD];
__device__ float                 g_AS[MTOT*HH];
__device__ float                 g_AD[MTOT*HH];
__device__ float                 g_ASP[32*MTOT];
__device__ float                 g_ADP[32*MTOT];
__device__ __align__(16) __half  g_QKVH[MTOT*3*DD];
__device__ __align__(16) __half  g_WQKVH[LTN*DD*3*DD];
__device__ float                 g_BQKV[LTN*3*DD];
__device__ __align__(16) __half  g_GATWH[LGN*HH*DD*DD];
__device__ __align__(16) __half  g_WOH[LTN*DD*DD];
__device__ __align__(16) __half  g_W1H[LTN*DD*DFFX];
__device__ __align__(16) __half  g_W2H[LTN*DFFX*DD];
__device__ __align__(16) __half  g_AOH[MTOT*DD];
__device__ float                 g_Y [MTOT*DD];
__device__ __align__(16) __half  g_YH[MTOT*DD];
__device__ __align__(16) __half  g_FFH[MTOT*DFFX];
__device__ unsigned              g_BITS[MTOT*(NNODE/32)];
__device__ int                   g_NBR[MTOT*NBCAP];
__device__ int                   g_CNT[MTOT];

// ---------------- helpers ----------------
__device__ __forceinline__ float block_sum256(float v, float* sm) {
    #pragma unroll
    for (int o = 16; o; o >>= 1) v += __shfl_xor_sync(0xffffffffu, v, o);
    int w = threadIdx.x >> 5;
    if ((threadIdx.x & 31) == 0) sm[w] = v;
    __syncthreads();
    if (threadIdx.x < 8) {
        v = sm[threadIdx.x];
        #pragma unroll
        for (int o = 4; o; o >>= 1) v += __shfl_xor_sync(0xffu, v, o);
        if (threadIdx.x == 0) sm[0] = v;
    }
    __syncthreads();
    v = sm[0];
    __syncthreads();
    return v;
}

__device__ __forceinline__ void mma_f16(float* c, const unsigned* a, const unsigned* b) {
    asm volatile(
        "mma.sync.aligned.m16n8k16.row.col.f32.f16.f16.f32 "
        "{%0,%1,%2,%3}, {%4,%5,%6,%7}, {%8,%9}, {%0,%1,%2,%3};\n"
        : "+f"(c[0]), "+f"(c[1]), "+f"(c[2]), "+f"(c[3])
        : "r"(a[0]), "r"(a[1]), "r"(a[2]), "r"(a[3]), "r"(b[0]), "r"(b[1]));
}

__device__ __forceinline__ unsigned saddr(const void* p) {
    return (unsigned)__cvta_generic_to_shared(p);
}
__device__ __forceinline__ void cp16(unsigned dst, const void* src) {
    asm volatile("cp.async.cg.shared.global [%0], [%1], 16;\n" :: "r"(dst), "l"(src));
}
__device__ __forceinline__ void cp_commit() {
    asm volatile("cp.async.commit_group;\n" ::: "memory");
}
template<int N>
__device__ __forceinline__ void cp_wait() {
    asm volatile("cp.async.wait_group %0;\n" :: "n"(N) : "memory");
}
__device__ __forceinline__ void ldsm4(unsigned& r0, unsigned& r1, unsigned& r2, unsigned& r3,
                                      unsigned addr) {
    asm volatile("ldmatrix.sync.aligned.m8n8.x4.shared.b16 {%0,%1,%2,%3}, [%4];"
                 : "=r"(r0), "=r"(r1), "=r"(r2), "=r"(r3) : "r"(addr));
}
__device__ __forceinline__ void ldsm4t(unsigned& r0, unsigned& r1, unsigned& r2, unsigned& r3,
                                       unsigned addr) {
    asm volatile("ldmatrix.sync.aligned.m8n8.x4.trans.shared.b16 {%0,%1,%2,%3}, [%4];"
                 : "=r"(r0), "=r"(r1), "=r"(r2), "=r"(r3) : "r"(addr));
}

// ---------------- adjacency pack ----------------
__global__ void pack_adj_k(const int* __restrict__ mask, unsigned* __restrict__ bits) {
    int idx = blockIdx.x * blockDim.x + threadIdx.x;
    int t  = idx & (NNODE - 1);
    int sw = (idx >> 10) & 31;
    int b  = idx >> 15;
    const int* mp = mask + ((size_t)b * NNODE + (size_t)sw * 32) * NNODE + t;
    unsigned w = 0;
    #pragma unroll
    for (int i = 0; i < 32; i++)
        if (mp[(size_t)i * NNODE] > 0) w |= (1u << i);
    int s0 = sw * 32;
    if (t >= s0 && t < s0 + 32) w |= (1u << (t - s0));
    bits[(b * NNODE + t) * 32 + sw] = w;
}

// ---------------- neighbor list build ----------------
__global__ void build_nbr_k(const unsigned* __restrict__ bits,
                            int* __restrict__ nbr, int* __restrict__ cnt) {
    int bt = blockIdx.x * blockDim.x + threadIdx.x;
    if (bt >= MTOT) return;
    const unsigned* bw = bits + (size_t)bt * 32;
    int* np = nbr + (size_t)bt * NBCAP;
    int c = 0;
    #pragma unroll 4
    for (int w = 0; w < 32; w++) {
        unsigned m = bw[w];
        while (m) {
            int bit = __ffs(m) - 1;
            m &= m - 1;
            if (c < NBCAP) np[c] = w * 32 + bit;
            c++;
        }
    }
    cnt[bt] = c < NBCAP ? c : NBCAP;
}

// ---------------- generic fp32 -> fp16 convert ----------------
__global__ void cvt_half_k(const float* __restrict__ src, __half* __restrict__ dst, int n) {
    int i = blockIdx.x * 256 + threadIdx.x;
    if (i * 4 >= n) return;
    float4 v = *(const float4*)(src + i * 4);
    __half2 a = __floats2half2_rn(v.x, v.y);
    __half2 b = __floats2half2_rn(v.z, v.w);
    *(__half2*)(dst + i * 4)     = a;
    *(__half2*)(dst + i * 4 + 2) = b;
}

// ---------------- QKV pack (fp16 weights + fp32 bias) ----------------
__global__ void pack_qkv_k(const float* __restrict__ Wq, const float* __restrict__ Wk,
                           const float* __restrict__ Wv, const float* __restrict__ bq,
                           const float* __restrict__ bk, const float* __restrict__ bv,
                           __half* __restrict__ W, float* __restrict__ Bb)
{
    int idx = blockIdx.x * 256 + threadIdx.x;
    if (idx >= LTN * DD * 3 * DD) return;
    int n = idx % (3 * DD);
    int k = (idx / (3 * DD)) % DD;
    int l = idx / (3 * DD * DD);
    float v;
    if (n < DD)            v = Wq[((size_t)l * DD + k) * DD + n];
    else if (n < 2 * DD)   v = Wk[((size_t)l * DD + k) * DD + n - DD];
    else                   v = Wv[((size_t)l * DD + k) * DD + n - 2 * DD];
    W[idx] = __float2half_rn(v);
    if (k == 0) {
        float bvv;
        if (n < DD)          bvv = bq[l * DD + n];
        else if (n < 2 * DD) bvv = bk[l * DD + n - DD];
        else                 bvv = bv[l * DD + n - 2 * DD];
        Bb[l * 3 * DD + n] = bvv;
    }
}

// ---------------- fp16 tensor-core GEMM: cp.async + ldmatrix ----------------
// C[M,N] = A[M,K] @ op(B) (+bias)(relu if ACT). A,B fp16. op(B)=B^T if BT (B [N,K]).
// HALF_OUT: C is __half. ASAD: per-64col-tile partial dots with attS/attD.
template<bool BT, int ACT, int HALF_OUT, int ASAD>
__global__ void __launch_bounds__(256) hgemm_k(
    int M, int Ncol, int K,
    const __half* __restrict__ A, int lda,
    const __half* __restrict__ B, int ldb,
    void* __restrict__ Cv, int ldc,
    const float* __restrict__ bias,
    const float* __restrict__ attS, const float* __restrict__ attD,
    float* __restrict__ ASP, float* __restrict__ ADP)
{
    __shared__ __align__(16) __half sA[2][128 * 24];
    __shared__ __align__(16) __half sB[2][3072];   // BT: [128][24]; !BT: [16][136]
    const int tid  = threadIdx.x;
    const int lane = tid & 31, wid = tid >> 5;
    const int wm = wid & 3, wn = wid >> 2;
    const int m0 = blockIdx.y * 128, n0 = blockIdx.x * 128;
    const int r = lane >> 2, cq = lane & 3;

    float acc[2][8][4];
    #pragma unroll
    for (int mt = 0; mt < 2; mt++)
        #pragma unroll
        for (int nt = 0; nt < 8; nt++)
            #pragma unroll
            for (int u = 0; u < 4; u++) acc[mt][nt][u] = 0.f;

    const int T = K / 16;

    auto loadT = [&](int st, int k0) {
        { // A: 128 rows x 16 halves = 256 x 16B chunks
            int m = tid >> 1, c = tid & 1;
            cp16(saddr(&sA[st][m * 24 + c * 8]), A + (size_t)(m0 + m) * lda + k0 + c * 8);
        }
        if (BT) {
            int n = tid >> 1, c = tid & 1;
            cp16(saddr(&sB[st][n * 24 + c * 8]), B + (size_t)(n0 + n) * ldb + k0 + c * 8);
        } else {
            int kk = tid >> 4, c = tid & 15;
            cp16(saddr(&sB[st][kk * 136 + c * 8]), B + (size_t)(k0 + kk) * ldb + n0 + c * 8);
        }
        cp_commit();
    };

    loadT(0, 0);
    for (int t = 0; t < T; t++) {
        if (t + 1 < T) { loadT((t + 1) & 1, (t + 1) * 16); cp_wait<1>(); }
        else           { cp_wait<0>(); }
        __syncthreads();
        const int st = t & 1;

        unsigned af[2][4], bf[8][2];
        #pragma unroll
        for (int mt = 0; mt < 2; mt++) {
            int mrow = wm * 32 + mt * 16;
            unsigned addr = saddr(&sA[st][(mrow + (lane & 15)) * 24 + (lane >> 4) * 8]);
            ldsm4(af[mt][0], af[mt][1], af[mt][2], af[mt][3], addr);
        }
        #pragma unroll
        for (int p = 0; p < 4; p++) {
            int nb = wn * 64 + p * 16;
            if (BT) {
                int row = nb + (lane & 7) + ((lane >> 4) << 3);
                int col = ((lane >> 3) & 1) * 8;
                unsigned addr = saddr(&sB[st][row * 24 + col]);
                ldsm4(bf[2 * p][0], bf[2 * p][1], bf[2 * p + 1][0], bf[2 * p + 1][1], addr);
            } else {
                int krow = (lane & 7) + (((lane >> 3) & 1) << 3);
                int coln = nb + (lane >> 4) * 8;
                unsigned addr = saddr(&sB[st][krow * 136 + coln]);
                ldsm4t(bf[2 * p][0], bf[2 * p][1], bf[2 * p + 1][0], bf[2 * p + 1][1], addr);
            }
        }
        #pragma unroll
        for (int mt = 0; mt < 2; mt++)
            #pragma unroll
            for (int nt = 0; nt < 8; nt++)
                mma_f16(acc[mt][nt], af[mt], bf[nt]);
        __syncthreads();
    }

    // ---- optional asad partial dots ----
    if (ASAD) {
        float sS[2][2] = {{0,0},{0,0}}, sD[2][2] = {{0,0},{0,0}};
        #pragma unroll
        for (int mt = 0; mt < 2; mt++)
            #pragma unroll
            for (int nt = 0; nt < 8; nt++)
                #pragma unroll
                for (int u = 0; u < 4; u++) {
                    int g = n0 + wn * 64 + nt * 8 + cq * 2 + (u & 1);
                    float v = acc[mt][nt][u];
                    sS[mt][u >> 1] += v * attS[g];
                    sD[mt][u >> 1] += v * attD[g];
                }
        #pragma unroll
        for (int o = 1; o <= 2; o <<= 1)
            #pragma unroll
            for (int mt = 0; mt < 2; mt++)
                #pragma unroll
                for (int q = 0; q < 2; q++) {
                    sS[mt][q] += __shfl_xor_sync(0xffffffffu, sS[mt][q], o);
                    sD[mt][q] += __shfl_xor_sync(0xffffffffu, sD[mt][q], o);
                }
        if (cq == 0) {
            int j = (n0 >> 6) + wn;
            #pragma unroll
            for (int mt = 0; mt < 2; mt++)
                #pragma unroll
                for (int q = 0; q < 2; q++) {
                    int row = m0 + wm * 32 + mt * 16 + r + q * 8;
                    ASP[(size_t)j * M + row] = sS[mt][q];
                    ADP[(size_t)j * M + row] = sD[mt][q];
                }
        }
    }

    // ---- epilogue ----
    #pragma unroll
    for (int mt = 0; mt < 2; mt++) {
        int mrow = m0 + wm * 32 + mt * 16 + r;
        #pragma unroll
        for (int nt = 0; nt < 8; nt++) {
            int ncol = n0 + wn * 64 + nt * 8 + cq * 2;
            float* ac = acc[mt][nt];
            float2 v0 = make_float2(ac[0], ac[1]);
            float2 v1 = make_float2(ac[2], ac[3]);
            if (bias) {
                float b0 = bias[ncol], b1 = bias[ncol + 1];
                v0.x += b0; v0.y += b1; v1.x += b0; v1.y += b1;
            }
            if (ACT == 1) {
                v0.x = fmaxf(v0.x, 0.f); v0.y = fmaxf(v0.y, 0.f);
                v1.x = fmaxf(v1.x, 0.f); v1.y = fmaxf(v1.y, 0.f);
            }
            if (HALF_OUT) {
                __half* Ch = (__half*)Cv;
                *(__half2*)(Ch + (size_t)mrow * ldc + ncol) = __floats2half2_rn(v0.x, v0.y);
                *(__half2*)(Ch + (size_t)(mrow + 8) * ldc + ncol) = __floats2half2_rn(v1.x, v1.y);
            } else {
                float* Cf = (float*)Cv;
                *(float2*)(Cf + (size_t)mrow * ldc + ncol) = v0;
                *(float2*)(Cf + (size_t)(mrow + 8) * ldc + ncol) = v1;
            }
        }
    }
}

// ---------------- asad reduce ----------------
__global__ void asad_reduce_k(const float* __restrict__ ASP, const float* __restrict__ ADP,
                              float* __restrict__ as_, float* __restrict__ ad_)
{
    int idx = blockIdx.x * 256 + threadIdx.x;
    int row = idx >> 3, h = idx & 7;
    float s = 0.f, d = 0.f;
    #pragma unroll
    for (int j = 4 * h; j < 4 * h + 4; j++) {
        s += ASP[(size_t)j * MTOT + row];
        d += ADP[(size_t)j * MTOT + row];
    }
    as_[row * 8 + h] = s;
    ad_[row * 8 + h] = d;
}

// ---------------- sparse GAT aggregation (fp16 features; writes fp32 + fp16) ----------------
__global__ void __launch_bounds__(256) gat_agg_k(
    const __half* __restrict__ hb, const float* __restrict__ as_,
    const float* __restrict__ ad_, const int* __restrict__ nbr,
    const int* __restrict__ cnt, const float* __restrict__ bias,
    float* __restrict__ y, __half* __restrict__ yh)
{
    __shared__ int   s_nbr[NBCAP];
    __shared__ float s_alpha[HH][NBCAP];
    __shared__ float s_inv[HH];
    __shared__ float4 s_red[4][64];
    int bt  = blockIdx.x;
    int b   = bt >> 10;
    int tid = threadIdx.x;
    int nc  = cnt[bt];
    for (int j = tid; j < nc; j += 256) s_nbr[j] = nbr[(size_t)bt * NBCAP + j];
    __syncthreads();

    for (int j = tid; j < nc; j += 256) {
        int s = s_nbr[j];
        const float* ap = as_ + (size_t)(b * NNODE + s) * HH;
        #pragma unroll
        for (int h = 0; h < HH; h++) {
            float e = ad_[bt * HH + h] + ap[h];
            e = e >= 0.f ? e : 0.2f * e;
            s_alpha[h][j] = __expf(e);
        }
    }
    __syncthreads();

    int wid = tid >> 5, lane = tid & 31;
    {
        float sum = 0.f;
        for (int j = lane; j < nc; j += 32) sum += s_alpha[wid][j];
        #pragma unroll
        for (int o = 16; o; o >>= 1) sum += __shfl_xor_sync(0xffffffffu, sum, o);
        if (lane == 0) s_inv[wid] = 1.f / (8.f * sum);
    }
    __syncthreads();
    for (int j = tid; j < nc; j += 256) {
        #pragma unroll
        for (int h = 0; h < HH; h++) s_alpha[h][j] *= s_inv[h];
    }
    __syncthreads();

    int hp = tid >> 6;
    int h0 = hp * 2;
    int cg = tid & 63;
    int c4 = cg * 4;
    float a0 = 0.f, a1 = 0.f, a2 = 0.f, a3 = 0.f;
    for (int j = 0; j < nc; j++) {
        int s = s_nbr[j];
        const __half* base = hb + (size_t)(b * NNODE + s) * (HH * DD);
        float w0 = s_alpha[h0][j], w1 = s_alpha[h0 + 1][j];
        const __half2* p0 = (const __half2*)(base + h0 * DD + c4);
        const __half2* p1 = (const __half2*)(base + (h0 + 1) * DD + c4);
        float2 u0 = __half22float2(p0[0]), u1 = __half22float2(p0[1]);
        float2 w0v = __half22float2(p1[0]), w1v = __half22float2(p1[1]);
        a0 = fmaf(w0, u0.x, fmaf(w1, w0v.x, a0));
        a1 = fmaf(w0, u0.y, fmaf(w1, w0v.y, a1));
        a2 = fmaf(w0, u1.x, fmaf(w1, w1v.x, a2));
        a3 = fmaf(w0, u1.y, fmaf(w1, w1v.y, a3));
    }
    s_red[hp][cg] = make_float4(a0, a1, a2, a3);
    __syncthreads();
    {
        int c = tid;
        const float* r0 = (const float*)&s_red[0][c >> 2];
        const float* r1 = (const float*)&s_red[1][c >> 2];
        const float* r2 = (const float*)&s_red[2][c >> 2];
        const float* r3 = (const float*)&s_red[3][c >> 2];
        int u = c & 3;
        float v = r0[u] + r1[u] + r2[u] + r3[u] + bias[c];
        y[(size_t)bt * DD + c] = v;
        yh[(size_t)bt * DD + c] = __float2half_rn(v);
    }
}

// ---------------- sparse masked attention (fp16 QKV in, fp16 out) ----------------
__global__ void __launch_bounds__(256) attn_sparse_k(
    const __half* __restrict__ QKV, const int* __restrict__ nbr,
    const int* __restrict__ cnt, __half* __restrict__ Om)
{
    __shared__ int s_nbr[NBCAP];
    int bt  = blockIdx.x;
    int b   = bt >> 10;
    int tid = threadIdx.x;
    int nc  = cnt[bt];
    for (int j = tid; j < nc; j += 256) s_nbr[j] = nbr[(size_t)bt * NBCAP + j];
    __syncthreads();
    int h = tid >> 5, lane = tid & 31;
    const int LD3 = 3 * DD;
    float q = __half2float(QKV[(size_t)bt * LD3 + h * DHH + lane]) * 0.17677669529663687f;
    float accv = 0.f, accw = 0.f;
    int j = 0;
    for (; j + 4 <= nc; j += 4) {
        float d[4], vv[4];
        #pragma unroll
        for (int u = 0; u < 4; u++) {
            int s = s_nbr[j + u];
            size_t base = (size_t)(b * NNODE + s) * LD3 + h * DHH + lane;
            d[u]  = q * __half2float(QKV[base + DD]);
            vv[u] = __half2float(QKV[base + 2 * DD]);
        }
        #pragma unroll
        for (int o = 16; o; o >>= 1) {
            #pragma unroll
            for (int u = 0; u < 4; u++) d[u] += __shfl_xor_sync(0xffffffffu, d[u], o);
        }
        #pragma unroll
        for (int u = 0; u < 4; u++) {
            float w = __expf(d[u]);
            accv = fmaf(w, vv[u], accv);
            accw += w;
        }
    }
    for (; j < nc; j++) {
        int s = s_nbr[j];
        size_t base = (size_t)(b * NNODE + s) * LD3 + h * DHH + lane;
        float d = q * __half2float(QKV[base + DD]);
        float vvv = __half2float(QKV[base + 2 * DD]);
        #pragma unroll
        for (int o = 16; o; o >>= 1) d += __shfl_xor_sync(0xffffffffu, d, o);
        float w = __expf(d);
        accv = fmaf(w, vvv, accv);
        accw += w;
    }
    Om[(size_t)bt * DD + h * DHH + lane] = __float2half_rn(accv / accw);
}

// ---------------- layernorm (optional relu on bsrc; optional fp16 shadow out) ----------------
template<int MODE, int WRITEH>
__global__ void ln_k(const float* __restrict__ a, const float* __restrict__ bsrc,
                     const float* __restrict__ gam, const float* __restrict__ bet,
                     float* __restrict__ out, __half* __restrict__ outh)
{
    __shared__ float sm[8];
    size_t row = blockIdx.x;
    int i = threadIdx.x;
    float v = a[row * DD + i];
    float w = bsrc[row * DD + i];
    if (MODE == 1) w = fmaxf(w, 0.f);
    v += w;
    float mean = block_sum256(v, sm) * (1.f / DD);
    float d = v - mean;
    float var = block_sum256(d * d, sm) * (1.f / DD);
    float o = d * rsqrtf(var + 1e-5f) * gam[i] + bet[i];
    out[row * DD + i] = o;
    if (WRITEH) outh[row * DD + i] = __float2half_rn(o);
}

extern "C" void kernel_launch(void* const* d_in, const int* in_sizes, int n_in,
                              void* d_out, int out_size)
{
    const float* emb  = (const float*)d_in[0];
    const int*   mask = (const int*)  d_in[2];
    const float* gatW = (const float*)d_in[4];
    const float* attS = (const float*)d_in[5];
    const float* attD = (const float*)d_in[6];
    const float* gatB = (const float*)d_in[7];
    const float* glnS = (const float*)d_in[8];
    const float* glnB = (const float*)d_in[9];
    const float* Wq = (const float*)d_in[10], *bq = (const float*)d_in[11];
    const float* Wk = (const float*)d_in[12], *bk = (const float*)d_in[13];
    const float* Wv = (const float*)d_in[14], *bv = (const float*)d_in[15];
    const float* Wo = (const float*)d_in[16], *bo = (const float*)d_in[17];
    const float* W1 = (const float*)d_in[18], *b1 = (const float*)d_in[19];
    const float* W2 = (const float*)d_in[20], *b2 = (const float*)d_in[21];
    const float* l1s = (const float*)d_in[22], *l1b = (const float*)d_in[23];
    const float* l2s = (const float*)d_in[24], *l2b = (const float*)d_in[25];
    float* out = (float*)d_out;

    float *XC,*AS,*AD,*ASP,*ADP,*BQKV,*Y;
    __half *XCH,*EMBH,*HBH,*QKVH,*WQKVH,*GATWH,*WOH,*W1H,*W2H,*AOH,*YH,*FFH;
    unsigned* BITS; int *NBR,*CNT;
    cudaGetSymbolAddress((void**)&XC, g_XC);
    cudaGetSymbolAddress((void**)&XCH, g_XCH);
    cudaGetSymbolAddress((void**)&EMBH, g_EMBH);
    cudaGetSymbolAddress((void**)&HBH, g_HBH);
    cudaGetSymbolAddress((void**)&AS, g_AS);
    cudaGetSymbolAddress((void**)&AD, g_AD);
    cudaGetSymbolAddress((void**)&ASP, g_ASP);
    cudaGetSymbolAddress((void**)&ADP, g_ADP);
    cudaGetSymbolAddress((void**)&QKVH, g_QKVH);
    cudaGetSymbolAddress((void**)&WQKVH, g_WQKVH);
    cudaGetSymbolAddress((void**)&BQKV, g_BQKV);
    cudaGetSymbolAddress((void**)&GATWH, g_GATWH);
    cudaGetSymbolAddress((void**)&WOH, g_WOH);
    cudaGetSymbolAddress((void**)&W1H, g_W1H);
    cudaGetSymbolAddress((void**)&W2H, g_W2H);
    cudaGetSymbolAddress((void**)&AOH, g_AOH);
    cudaGetSymbolAddress((void**)&Y,  g_Y);
    cudaGetSymbolAddress((void**)&YH, g_YH);
    cudaGetSymbolAddress((void**)&FFH, g_FFH);
    cudaGetSymbolAddress((void**)&BITS, g_BITS);
    cudaGetSymbolAddress((void**)&NBR, g_NBR);
    cudaGetSymbolAddress((void**)&CNT, g_CNT);

    const int M = MTOT;

    pack_adj_k<<<(BB*32*NNODE)/256, 256>>>(mask, BITS);
    build_nbr_k<<<(MTOT)/256, 256>>>(BITS, NBR, CNT);
    pack_qkv_k<<<(LTN*DD*3*DD + 255)/256, 256>>>(Wq, Wk, Wv, bq, bk, bv, WQKVH, BQKV);
    cvt_half_k<<<(MTOT*DD/4 + 255)/256, 256>>>(emb, EMBH, MTOT*DD);
    cvt_half_k<<<(LGN*HH*DD*DD/4 + 255)/256, 256>>>(gatW, GATWH, LGN*HH*DD*DD);
    cvt_half_k<<<(LTN*DD*DD/4 + 255)/256, 256>>>(Wo, WOH, LTN*DD*DD);
    cvt_half_k<<<(LTN*DD*DFFX/4 + 255)/256, 256>>>(W1, W1H, LTN*DD*DFFX);
    cvt_half_k<<<(LTN*DFFX*DD/4 + 255)/256, 256>>>(W2, W2H, LTN*DFFX*DD);

    // ---- GAT stack ----
    const __half* x = EMBH;
    for (int l = 0; l < LGN; l++) {
        hgemm_k<true,0,1,1><<<dim3((HH*DD)/128, M/128), 256>>>(
            M, HH*DD, DD, x, DD, GATWH + (size_t)l*HH*DD*DD, DD,
            HBH, HH*DD, nullptr, attS + l*HH*DD, attD + l*HH*DD, ASP, ADP);
        asad_reduce_k<<<(MTOT*8)/256, 256>>>(ASP, ADP, AS, AD);
        gat_agg_k<<<M, 256>>>(HBH, AS, AD, NBR, CNT, gatB + l*DD, Y, YH);
        x = YH;
    }
    ln_k<1,1><<<M, 256>>>(emb, Y, glnS, glnB, XC, XCH);

    // ---- transformer layers ----
    for (int l = 0; l < LTN; l++) {
        hgemm_k<false,0,1,0><<<dim3((3*DD)/128, M/128), 256>>>(
            M, 3*DD, DD, XCH, DD, WQKVH + (size_t)l*DD*3*DD, 3*DD, QKVH, 3*DD,
            BQKV + l*3*DD, nullptr, nullptr, nullptr, nullptr);
        attn_sparse_k<<<M, 256>>>(QKVH, NBR, CNT, AOH);
        hgemm_k<false,0,0,0><<<dim3(DD/128, M/128), 256>>>(
            M, DD, DD, AOH, DD, WOH + (size_t)l*DD*DD, DD, Y, DD,
            bo + l*DD, nullptr, nullptr, nullptr, nullptr);
        ln_k<0,1><<<M, 256>>>(XC, Y, l1s + l*DD, l1b + l*DD, XC, XCH);
        hgemm_k<false,1,1,0><<<dim3(DFFX/128, M/128), 256>>>(
            M, DFFX, DD, XCH, DD, W1H + (size_t)l*DD*DFFX, DFFX, FFH, DFFX,
            b1 + l*DFFX, nullptr, nullptr, nullptr, nullptr);
        hgemm_k<false,0,0,0><<<dim3(DD/128, M/128), 256>>>(
            M, DD, DFFX, FFH, DFFX, W2H + (size_t)l*DFFX*DD, DD, Y, DD,
            b2 + l*DD, nullptr, nullptr, nullptr, nullptr);
        if (l == LTN - 1)
            ln_k<0,0><<<M, 256>>>(XC, Y, l2s + l*DD, l2b + l*DD, out, nullptr);
        else
            ln_k<0,1><<<M, 256>>>(XC, Y, l2s + l*DD, l2b + l*DD, XC, XCH);
    }
}